// round 1
// baseline (speedup 1.0000x reference)
#include <cuda_runtime.h>
#include <math.h>

#define B 8
#define S 8192
#define D 64
#define H 8
#define NB 128           // n_buckets per hash
#define BSZ 64           // bucket (chunk) size
#define CHUNKS 1024      // H * NB chunks per batch

// -------- device scratch (no allocations allowed) --------
__device__ unsigned char  g_bucket[B * H * S];          // 512 KB
__device__ unsigned short g_st[B * H * S];              // sorted token ids, 1 MB
__device__ float          g_logits[B * H * S];          // per-round lse, 2 MB
__device__ float          g_o[(size_t)B * H * S * D];   // per-round outputs, 128 MB

// ============================================================
// K1: LSH hashing.  rotated[b,h,t,i] = sum_f qk[b,t,f]*rot[f,h,i]
// bucket = argmax over concat([r, -r]) (first occurrence wins).
// ============================================================
__global__ __launch_bounds__(256) void hash_kernel(const float* __restrict__ qk,
                                                   const float* __restrict__ rot)
{
    int b = blockIdx.z, h = blockIdx.y, tile = blockIdx.x;
    __shared__ float srot[64 * 64];   // srot[f*64 + i] = rot[f, h, i]
    int tid = threadIdx.x;
    for (int idx = tid; idx < 64 * 64; idx += 256) {
        int f = idx >> 6, i = idx & 63;
        srot[idx] = rot[(size_t)f * (H * 64) + h * 64 + i];
    }
    __syncthreads();

    int t = tile * 256 + tid;
    float q[64];
    const float4* qr = (const float4*)(qk + ((size_t)b * S + t) * D);
#pragma unroll
    for (int i = 0; i < 16; i++) {
        float4 f4 = qr[i];
        q[4*i] = f4.x; q[4*i+1] = f4.y; q[4*i+2] = f4.z; q[4*i+3] = f4.w;
    }

    float bestP = -INFINITY, bestN = -INFINITY;
    int ip = 0, inn = 0;
    for (int i4 = 0; i4 < 16; i4++) {
        float a0 = 0.f, a1 = 0.f, a2 = 0.f, a3 = 0.f;
#pragma unroll
        for (int f = 0; f < 64; f++) {
            float4 r = *(const float4*)&srot[f * 64 + i4 * 4];
            a0 += q[f] * r.x; a1 += q[f] * r.y;
            a2 += q[f] * r.z; a3 += q[f] * r.w;
        }
        int base = i4 * 4;
        if (a0 > bestP) { bestP = a0; ip = base;     }
        if (a1 > bestP) { bestP = a1; ip = base + 1; }
        if (a2 > bestP) { bestP = a2; ip = base + 2; }
        if (a3 > bestP) { bestP = a3; ip = base + 3; }
        if (-a0 > bestN) { bestN = -a0; inn = base;     }
        if (-a1 > bestN) { bestN = -a1; inn = base + 1; }
        if (-a2 > bestN) { bestN = -a2; inn = base + 2; }
        if (-a3 > bestN) { bestN = -a3; inn = base + 3; }
    }
    // concatenated order [r, -r]: positive half comes first -> >= keeps it on ties
    int bucket = (bestP >= bestN) ? ip : (64 + inn);
    g_bucket[((size_t)b * H + h) * S + t] = (unsigned char)bucket;
}

// ============================================================
// K2: stable counting sort per (b,h): sort tokens by (bucket, t).
// One block of 128 threads; thread k owns bucket k.
// ============================================================
__global__ __launch_bounds__(128) void sort_kernel()
{
    int bh = blockIdx.x;               // b*H + h
    __shared__ unsigned char sb[S];    // 8 KB
    __shared__ int hist[NB];
    __shared__ int base[NB];
    int tid = threadIdx.x;

    hist[tid] = 0;
    __syncthreads();

    const uchar4* src = (const uchar4*)(g_bucket + (size_t)bh * S);
    for (int i = tid; i < S / 4; i += 128) {
        uchar4 u = src[i];
        ((uchar4*)sb)[i] = u;
        atomicAdd(&hist[u.x], 1);
        atomicAdd(&hist[u.y], 1);
        atomicAdd(&hist[u.z], 1);
        atomicAdd(&hist[u.w], 1);
    }
    __syncthreads();

    if (tid == 0) {
        int s = 0;
        for (int k = 0; k < NB; k++) { base[k] = s; s += hist[k]; }
    }
    __syncthreads();

    int myb = tid;
    int cnt = base[myb];
    unsigned short* dst = g_st + (size_t)bh * S;
    for (int i = 0; i < S; i += 4) {
        uchar4 u = *(const uchar4*)(sb + i);   // broadcast read
        if (u.x == myb) dst[cnt++] = (unsigned short)(i);
        if (u.y == myb) dst[cnt++] = (unsigned short)(i + 1);
        if (u.z == myb) dst[cnt++] = (unsigned short)(i + 2);
        if (u.w == myb) dst[cnt++] = (unsigned short)(i + 3);
    }
}

// ============================================================
// K3: bucketed attention.  One block per (b, chunk).
// Thread i owns query row i (64 rows).  K/V for the current and
// previous chunk are staged in shared (stride 68 floats: float4-
// aligned, conflict-light writes, broadcast reads).
// Online softmax; scatter results to g_o / g_logits (this IS the
// unsort, since each (b,h,token) occurs exactly once).
// ============================================================
__global__ __launch_bounds__(64) void attn_kernel(const float* __restrict__ qk,
                                                  const float* __restrict__ vin)
{
    int b = blockIdx.y, c = blockIdx.x;
    int h = c >> 7;
    int tid = threadIdx.x;

    __shared__ float sk[64 * 68];
    __shared__ float sv[64 * 68];
    __shared__ int   skid[64];

    const unsigned short* ST = g_st + (size_t)b * (H * S);
    int myTok = ST[c * BSZ + tid];

    float q[64];
    {
        const float4* qr = (const float4*)(qk + ((size_t)b * S + myTok) * D);
#pragma unroll
        for (int i = 0; i < 16; i++) {
            float4 f4 = qr[i];
            q[4*i] = f4.x; q[4*i+1] = f4.y; q[4*i+2] = f4.z; q[4*i+3] = f4.w;
        }
    }

    float m = -INFINITY, l = 0.f;
    float acc[64];
#pragma unroll
    for (int d = 0; d < 64; d++) acc[d] = 0.f;

    for (int half = 0; half < 2; half++) {
        int cc = (half == 0) ? c : ((c + CHUNKS - 1) & (CHUNKS - 1));
        int kt = ST[cc * BSZ + tid];
        skid[tid] = kt;

        // load + normalize K row
        const float4* kr = (const float4*)(qk + ((size_t)b * S + kt) * D);
        float kv[64];
        float ss = 0.f;
#pragma unroll
        for (int i = 0; i < 16; i++) {
            float4 f4 = kr[i];
            kv[4*i] = f4.x; kv[4*i+1] = f4.y; kv[4*i+2] = f4.z; kv[4*i+3] = f4.w;
            ss += f4.x*f4.x + f4.y*f4.y + f4.z*f4.z + f4.w*f4.w;
        }
        float rn = 1.f / fmaxf(sqrtf(ss), 1e-12f);
        float* kd = sk + tid * 68;
#pragma unroll
        for (int i = 0; i < 16; i++) {
            float4 o4 = make_float4(kv[4*i] * rn, kv[4*i+1] * rn,
                                    kv[4*i+2] * rn, kv[4*i+3] * rn);
            *(float4*)(kd + 4*i) = o4;
        }
        const float4* vr = (const float4*)(vin + ((size_t)b * S + kt) * D);
        float* vd = sv + tid * 68;
#pragma unroll
        for (int i = 0; i < 16; i++) *(float4*)(vd + 4*i) = vr[i];
        __syncthreads();

        for (int j = 0; j < 64; j++) {
            const float4* kj = (const float4*)(sk + j * 68);
            float s = 0.f;
#pragma unroll
            for (int d4 = 0; d4 < 16; d4++) {
                float4 kk = kj[d4];
                s += q[4*d4] * kk.x + q[4*d4+1] * kk.y
                   + q[4*d4+2] * kk.z + q[4*d4+3] * kk.w;
            }
            s *= 0.125f;                       // D^-0.5
            if (skid[j] == myTok) s = -50000.f;

            const float4* vj = (const float4*)(sv + j * 68);
            if (s > m) {
                float sc = __expf(m - s);      // exp(-inf)=0 handles first iter
                m = s;
                l = l * sc + 1.f;
#pragma unroll
                for (int d4 = 0; d4 < 16; d4++) {
                    float4 vv = vj[d4];
                    acc[4*d4]   = acc[4*d4]   * sc + vv.x;
                    acc[4*d4+1] = acc[4*d4+1] * sc + vv.y;
                    acc[4*d4+2] = acc[4*d4+2] * sc + vv.z;
                    acc[4*d4+3] = acc[4*d4+3] * sc + vv.w;
                }
            } else {
                float p = __expf(s - m);
                l += p;
#pragma unroll
                for (int d4 = 0; d4 < 16; d4++) {
                    float4 vv = vj[d4];
                    acc[4*d4]   += p * vv.x;
                    acc[4*d4+1] += p * vv.y;
                    acc[4*d4+2] += p * vv.z;
                    acc[4*d4+3] += p * vv.w;
                }
            }
        }
        __syncthreads();
    }

    float inv = 1.f / l;
    float* orow = g_o + (((size_t)(b * H + h) * S + myTok) * D);
#pragma unroll
    for (int i = 0; i < 16; i++) {
        float4 o4 = make_float4(acc[4*i] * inv, acc[4*i+1] * inv,
                                acc[4*i+2] * inv, acc[4*i+3] * inv);
        *(float4*)(orow + 4*i) = o4;
    }
    g_logits[((size_t)(b * H + h)) * S + myTok] = m + __logf(l);
}

// ============================================================
// K4: combine the H rounds with softmax(logits) weights.
// One 64-thread block per (b, token).
// ============================================================
__global__ __launch_bounds__(64) void combine_kernel(float* __restrict__ out)
{
    int bt = blockIdx.x;
    int b = bt >> 13, t = bt & (S - 1);
    int d = threadIdx.x;

    float lg[H];
    float mx = -INFINITY;
#pragma unroll
    for (int h = 0; h < H; h++) {
        lg[h] = g_logits[((size_t)(b * H + h)) * S + t];
        mx = fmaxf(mx, lg[h]);
    }
    float sum = 0.f;
#pragma unroll
    for (int h = 0; h < H; h++) { lg[h] = __expf(lg[h] - mx); sum += lg[h]; }

    float a = 0.f;
#pragma unroll
    for (int h = 0; h < H; h++)
        a += lg[h] * g_o[(((size_t)(b * H + h)) * S + t) * D + d];

    out[((size_t)b * S + t) * D + d] = a / sum;
}

// ============================================================
extern "C" void kernel_launch(void* const* d_in, const int* in_sizes, int n_in,
                              void* d_out, int out_size)
{
    const float* qk  = (const float*)d_in[0];
    const float* v   = (const float*)d_in[1];
    const float* rot = (const float*)d_in[2];
    float* out = (float*)d_out;

    hash_kernel<<<dim3(32, H, B), 256>>>(qk, rot);
    sort_kernel<<<B * H, 128>>>();
    attn_kernel<<<dim3(CHUNKS, B), 64>>>(qk, v);
    combine_kernel<<<B * S, 64>>>(out);
}

// round 2
// speedup vs baseline: 1.1691x; 1.1691x over previous
#include <cuda_runtime.h>
#include <math.h>

#define B 8
#define S 8192
#define D 64
#define H 8
#define NB 128           // n_buckets per hash
#define BSZ 64           // bucket (chunk) size
#define CHUNKS 1024      // H * NB chunks per batch

typedef unsigned long long ull;

// ---------- packed f32x2 helpers (sm_100+) ----------
__device__ __forceinline__ ull fma2(ull a, ull b, ull c) {
    ull d; asm("fma.rn.f32x2 %0, %1, %2, %3;" : "=l"(d) : "l"(a), "l"(b), "l"(c)); return d;
}
__device__ __forceinline__ ull add2(ull a, ull b) {
    ull d; asm("add.rn.f32x2 %0, %1, %2;" : "=l"(d) : "l"(a), "l"(b)); return d;
}
__device__ __forceinline__ ull mul2(ull a, ull b) {
    ull d; asm("mul.rn.f32x2 %0, %1, %2;" : "=l"(d) : "l"(a), "l"(b)); return d;
}
__device__ __forceinline__ ull pack2(float x, float y) {
    ull r; asm("mov.b64 %0, {%1,%2};" : "=l"(r) : "f"(x), "f"(y)); return r;
}
__device__ __forceinline__ void unpack2(float& x, float& y, ull r) {
    asm("mov.b64 {%0,%1}, %2;" : "=f"(x), "=f"(y) : "l"(r));
}

// -------- device scratch (no allocations allowed) --------
__device__ unsigned char  g_bucket[B * H * S];          // 512 KB
__device__ unsigned short g_st[B * H * S];              // sorted token ids, 1 MB
__device__ float          g_logits[B * H * S];          // per-round lse, 2 MB
__device__ float          g_o[(size_t)B * H * S * D];   // per-round outputs, 128 MB

// ============================================================
// K1: LSH hashing with packed f32x2 matvec.
// bucket = argmax over concat([r, -r]) (first occurrence wins).
// ============================================================
__global__ __launch_bounds__(256) void hash_kernel(const float* __restrict__ qk,
                                                   const float* __restrict__ rot)
{
    int b = blockIdx.z, h = blockIdx.y, tile = blockIdx.x;
    __shared__ float srot[64 * 64];   // srot[f*64 + i] = rot[f, h, i]
    int tid = threadIdx.x;
    for (int idx = tid; idx < 64 * 64; idx += 256) {
        int f = idx >> 6, i = idx & 63;
        srot[idx] = rot[(size_t)f * (H * 64) + h * 64 + i];
    }
    __syncthreads();

    int t = tile * 256 + tid;
    float q[64];
    const float4* qr = (const float4*)(qk + ((size_t)b * S + t) * D);
#pragma unroll
    for (int i = 0; i < 16; i++) {
        float4 f4 = qr[i];
        q[4*i] = f4.x; q[4*i+1] = f4.y; q[4*i+2] = f4.z; q[4*i+3] = f4.w;
    }

    float bestP = -INFINITY, bestN = -INFINITY;
    int ip = 0, inn = 0;
#pragma unroll
    for (int g = 0; g < 4; g++) {          // 16 outputs per group = 8 packed
        ull a2[8];
#pragma unroll
        for (int k = 0; k < 8; k++) a2[k] = 0ull;
        for (int f = 0; f < 64; f++) {
            ull qq = pack2(q[f], q[f]);
            const ulonglong2* rp = (const ulonglong2*)&srot[f * 64 + g * 16];
#pragma unroll
            for (int k = 0; k < 4; k++) {
                ulonglong2 u = rp[k];
                a2[2*k]   = fma2(qq, u.x, a2[2*k]);
                a2[2*k+1] = fma2(qq, u.y, a2[2*k+1]);
            }
        }
        // a2[2k]   -> indices g*16 + 4k,   g*16 + 4k+1
        // a2[2k+1] -> indices g*16 + 4k+2, g*16 + 4k+3   (ascending order)
#pragma unroll
        for (int m = 0; m < 8; m++) {
            float lo, hi; unpack2(lo, hi, a2[m]);
            int idx = g * 16 + 4 * (m >> 1) + 2 * (m & 1);
            if (lo > bestP)  { bestP = lo;  ip  = idx;     }
            if (hi > bestP)  { bestP = hi;  ip  = idx + 1; }
            if (-lo > bestN) { bestN = -lo; inn = idx;     }
            if (-hi > bestN) { bestN = -hi; inn = idx + 1; }
        }
    }
    // concatenated order [r, -r]: positive half first -> >= keeps it on ties
    int bucket = (bestP >= bestN) ? ip : (64 + inn);
    g_bucket[((size_t)b * H + h) * S + t] = (unsigned char)bucket;
}

// ============================================================
// K2: stable counting sort per (b,h): sort tokens by (bucket, t).
// ============================================================
__global__ __launch_bounds__(128) void sort_kernel()
{
    int bh = blockIdx.x;               // b*H + h
    __shared__ unsigned char sb[S];    // 8 KB
    __shared__ int hist[NB];
    __shared__ int base[NB];
    int tid = threadIdx.x;

    hist[tid] = 0;
    __syncthreads();

    const uchar4* src = (const uchar4*)(g_bucket + (size_t)bh * S);
    for (int i = tid; i < S / 4; i += 128) {
        uchar4 u = src[i];
        ((uchar4*)sb)[i] = u;
        atomicAdd(&hist[u.x], 1);
        atomicAdd(&hist[u.y], 1);
        atomicAdd(&hist[u.z], 1);
        atomicAdd(&hist[u.w], 1);
    }
    __syncthreads();

    if (tid == 0) {
        int s = 0;
        for (int k = 0; k < NB; k++) { base[k] = s; s += hist[k]; }
    }
    __syncthreads();

    int myb = tid;
    int cnt = base[myb];
    unsigned short* dst = g_st + (size_t)bh * S;
    for (int i = 0; i < S; i += 4) {
        uchar4 u = *(const uchar4*)(sb + i);   // broadcast read
        if (u.x == myb) dst[cnt++] = (unsigned short)(i);
        if (u.y == myb) dst[cnt++] = (unsigned short)(i + 1);
        if (u.z == myb) dst[cnt++] = (unsigned short)(i + 2);
        if (u.w == myb) dst[cnt++] = (unsigned short)(i + 3);
    }
}

// ============================================================
// K3: bucketed attention, 128 threads/block.
//  - threads 0..63  : query rows 0..63, keys 0..63   (chunk c)
//  - threads 64..127: query rows 0..63, keys 64..127 (prev chunk)
// Both chunks' K (raw) + V staged in smem once; per-row scale
// srn = 0.125/max(||k||,eps) folded into the score.
// No online softmax: scores are bounded (|s| <= |q|/8 ~ 1.6),
// exp() cannot overflow.  Partials merged through dead sk region.
// ============================================================
__global__ __launch_bounds__(128) void attn_kernel(const float* __restrict__ qk,
                                                   const float* __restrict__ vin)
{
    int b = blockIdx.y, c = blockIdx.x;
    int h = c >> 7;
    int tid = threadIdx.x;
    int row = tid & 63;
    int halfsel = tid >> 6;

    extern __shared__ float smem[];
    float* sk   = smem;                  // 128 * 68
    float* sv   = smem + 8704;           // 128 * 68
    float* srn  = smem + 17408;          // 128
    int*   skid = (int*)(smem + 17536);  // 128

    const unsigned short* ST = g_st + (size_t)b * (H * S);
    int myTok = ST[c * BSZ + row];

    // --- stage K (raw) + per-row scale + V for slot tid ---
    int kc = halfsel ? ((c + CHUNKS - 1) & (CHUNKS - 1)) : c;
    int kt = ST[kc * BSZ + row];
    skid[tid] = kt;
    {
        const float4* kr = (const float4*)(qk + ((size_t)b * S + kt) * D);
        float* kd = sk + tid * 68;
        float ss = 0.f;
#pragma unroll
        for (int i = 0; i < 16; i++) {
            float4 f4 = kr[i];
            ss += f4.x*f4.x + f4.y*f4.y + f4.z*f4.z + f4.w*f4.w;
            *(float4*)(kd + 4*i) = f4;
        }
        srn[tid] = 0.125f / fmaxf(sqrtf(ss), 1e-12f);
        const float4* vr = (const float4*)(vin + ((size_t)b * S + kt) * D);
        float* vd = sv + tid * 68;
#pragma unroll
        for (int i = 0; i < 16; i++) *(float4*)(vd + 4*i) = vr[i];
    }

    // --- q row in packed registers ---
    ull qp[32];
    {
        const ulonglong2* qr = (const ulonglong2*)(qk + ((size_t)b * S + myTok) * D);
#pragma unroll
        for (int i = 0; i < 16; i++) { ulonglong2 u = qr[i]; qp[2*i] = u.x; qp[2*i+1] = u.y; }
    }
    __syncthreads();

    ull acc2[32];
#pragma unroll
    for (int i = 0; i < 32; i++) acc2[i] = 0ull;
    float l = 0.f;

    int jbase = halfsel << 6;
    for (int jj = 0; jj < 64; jj++) {
        int j = jbase + jj;
        const ulonglong2* kj = (const ulonglong2*)(sk + j * 68);
        ull d0 = 0ull, d1 = 0ull, d2 = 0ull, d3 = 0ull;
#pragma unroll
        for (int i = 0; i < 8; i++) {
            ulonglong2 u0 = kj[2*i], u1 = kj[2*i+1];
            d0 = fma2(qp[4*i],   u0.x, d0);
            d1 = fma2(qp[4*i+1], u0.y, d1);
            d2 = fma2(qp[4*i+2], u1.x, d2);
            d3 = fma2(qp[4*i+3], u1.y, d3);
        }
        d0 = add2(add2(d0, d1), add2(d2, d3));
        float lo, hi; unpack2(lo, hi, d0);
        float s = (lo + hi) * srn[j];
        if (skid[j] == myTok) s = -50000.f;   // self-mask; exp -> 0
        float p = __expf(s);
        l += p;
        ull pp = pack2(p, p);
        const ulonglong2* vj = (const ulonglong2*)(sv + j * 68);
#pragma unroll
        for (int i = 0; i < 16; i++) {
            ulonglong2 u = vj[i];
            acc2[2*i]   = fma2(pp, u.x, acc2[2*i]);
            acc2[2*i+1] = fma2(pp, u.y, acc2[2*i+1]);
        }
    }
    __syncthreads();     // everyone done reading sk/sv/srn

    if (halfsel) {       // upper half dumps partials into dead sk region
        ull* red = (ull*)(sk + row * 68);
#pragma unroll
        for (int i = 0; i < 32; i++) red[i] = acc2[i];
        srn[row] = l;
    }
    __syncthreads();

    if (!halfsel) {
        const ull* red = (const ull*)(sk + row * 68);
#pragma unroll
        for (int i = 0; i < 32; i++) acc2[i] = add2(acc2[i], red[i]);
        l += srn[row];

        float inv = 1.f / l;
        ull ip2 = pack2(inv, inv);
        float* orow = g_o + (((size_t)(b * H + h) * S + myTok) * D);
#pragma unroll
        for (int i = 0; i < 16; i++) {
            ulonglong2 o2;
            o2.x = mul2(acc2[2*i],   ip2);
            o2.y = mul2(acc2[2*i+1], ip2);
            *(ulonglong2*)(orow + 4*i) = o2;
        }
        g_logits[((size_t)(b * H + h)) * S + myTok] = __logf(l);
    }
}

// ============================================================
// K4: combine the H rounds with softmax(logits) weights.
// 256 threads/block = 4 tokens/block.
// ============================================================
__global__ __launch_bounds__(256) void combine_kernel(float* __restrict__ out)
{
    int bt = blockIdx.x * 4 + (threadIdx.x >> 6);
    int b = bt >> 13, t = bt & (S - 1);
    int d = threadIdx.x & 63;

    float lg[H];
    float mx = -INFINITY;
#pragma unroll
    for (int h = 0; h < H; h++) {
        lg[h] = g_logits[((size_t)(b * H + h)) * S + t];
        mx = fmaxf(mx, lg[h]);
    }
    float sum = 0.f;
#pragma unroll
    for (int h = 0; h < H; h++) { lg[h] = __expf(lg[h] - mx); sum += lg[h]; }

    float a = 0.f;
#pragma unroll
    for (int h = 0; h < H; h++)
        a += lg[h] * g_o[(((size_t)(b * H + h)) * S + t) * D + d];

    out[((size_t)b * S + t) * D + d] = a / sum;
}

// ============================================================
extern "C" void kernel_launch(void* const* d_in, const int* in_sizes, int n_in,
                              void* d_out, int out_size)
{
    const float* qk  = (const float*)d_in[0];
    const float* v   = (const float*)d_in[1];
    const float* rot = (const float*)d_in[2];
    float* out = (float*)d_out;

    static int smem_set = 0;
    (void)smem_set; // attribute set is idempotent & deterministic
    cudaFuncSetAttribute(attn_kernel, cudaFuncAttributeMaxDynamicSharedMemorySize, 70656);

    hash_kernel<<<dim3(32, H, B), 256>>>(qk, rot);
    sort_kernel<<<B * H, 128>>>();
    attn_kernel<<<dim3(CHUNKS, B), 128, 70656>>>(qk, v);
    combine_kernel<<<B * S / 4, 256>>>(out);
}

// round 3
// speedup vs baseline: 1.3707x; 1.1724x over previous
#include <cuda_runtime.h>
#include <math.h>

#define B 8
#define S 8192
#define D 64
#define H 8
#define NB 128           // n_buckets per hash
#define BSZ 64           // bucket (chunk) size
#define CHUNKS 1024      // H * NB chunks per batch

typedef unsigned long long ull;

// ---------- packed f32x2 helpers (sm_100+) ----------
__device__ __forceinline__ ull fma2(ull a, ull b, ull c) {
    ull d; asm("fma.rn.f32x2 %0, %1, %2, %3;" : "=l"(d) : "l"(a), "l"(b), "l"(c)); return d;
}
__device__ __forceinline__ ull add2(ull a, ull b) {
    ull d; asm("add.rn.f32x2 %0, %1, %2;" : "=l"(d) : "l"(a), "l"(b)); return d;
}
__device__ __forceinline__ ull mul2(ull a, ull b) {
    ull d; asm("mul.rn.f32x2 %0, %1, %2;" : "=l"(d) : "l"(a), "l"(b)); return d;
}
__device__ __forceinline__ ull pack2(float x, float y) {
    ull r; asm("mov.b64 %0, {%1,%2};" : "=l"(r) : "f"(x), "f"(y)); return r;
}
__device__ __forceinline__ void unpack2(float& x, float& y, ull r) {
    asm("mov.b64 {%0,%1}, %2;" : "=f"(x), "=f"(y) : "l"(r));
}

// -------- device scratch (no allocations allowed) --------
__device__ unsigned char  g_bucket[B * H * S];          // 512 KB
__device__ unsigned short g_st[B * H * S];              // sorted token ids, 1 MB
__device__ float          g_logits[B * H * S];          // per-round lse, 2 MB
__device__ float          g_o[(size_t)B * H * S * D];   // per-round outputs, 128 MB

// ============================================================
// K1: LSH hashing with packed f32x2 matvec.
// ============================================================
__global__ __launch_bounds__(256) void hash_kernel(const float* __restrict__ qk,
                                                   const float* __restrict__ rot)
{
    int b = blockIdx.z, h = blockIdx.y, tile = blockIdx.x;
    __shared__ float srot[64 * 64];   // srot[f*64 + i] = rot[f, h, i]
    int tid = threadIdx.x;
    for (int idx = tid; idx < 64 * 64; idx += 256) {
        int f = idx >> 6, i = idx & 63;
        srot[idx] = rot[(size_t)f * (H * 64) + h * 64 + i];
    }
    __syncthreads();

    int t = tile * 256 + tid;
    float q[64];
    const float4* qr = (const float4*)(qk + ((size_t)b * S + t) * D);
#pragma unroll
    for (int i = 0; i < 16; i++) {
        float4 f4 = qr[i];
        q[4*i] = f4.x; q[4*i+1] = f4.y; q[4*i+2] = f4.z; q[4*i+3] = f4.w;
    }

    float bestP = -INFINITY, bestN = -INFINITY;
    int ip = 0, inn = 0;
#pragma unroll
    for (int g = 0; g < 4; g++) {          // 16 outputs per group = 8 packed
        ull a2[8];
#pragma unroll
        for (int k = 0; k < 8; k++) a2[k] = 0ull;
        for (int f = 0; f < 64; f++) {
            ull qq = pack2(q[f], q[f]);
            const ulonglong2* rp = (const ulonglong2*)&srot[f * 64 + g * 16];
#pragma unroll
            for (int k = 0; k < 4; k++) {
                ulonglong2 u = rp[k];
                a2[2*k]   = fma2(qq, u.x, a2[2*k]);
                a2[2*k+1] = fma2(qq, u.y, a2[2*k+1]);
            }
        }
#pragma unroll
        for (int m = 0; m < 8; m++) {
            float lo, hi; unpack2(lo, hi, a2[m]);
            int idx = g * 16 + 4 * (m >> 1) + 2 * (m & 1);
            if (lo > bestP)  { bestP = lo;  ip  = idx;     }
            if (hi > bestP)  { bestP = hi;  ip  = idx + 1; }
            if (-lo > bestN) { bestN = -lo; inn = idx;     }
            if (-hi > bestN) { bestN = -hi; inn = idx + 1; }
        }
    }
    int bucket = (bestP >= bestN) ? ip : (64 + inn);
    g_bucket[((size_t)b * H + h) * S + t] = (unsigned char)bucket;
}

// ============================================================
// K2: stable counting sort per (b,h): sort tokens by (bucket, t).
// ============================================================
__global__ __launch_bounds__(128) void sort_kernel()
{
    int bh = blockIdx.x;               // b*H + h
    __shared__ unsigned char sb[S];    // 8 KB
    __shared__ int hist[NB];
    __shared__ int base[NB];
    int tid = threadIdx.x;

    hist[tid] = 0;
    __syncthreads();

    const uchar4* src = (const uchar4*)(g_bucket + (size_t)bh * S);
    for (int i = tid; i < S / 4; i += 128) {
        uchar4 u = src[i];
        ((uchar4*)sb)[i] = u;
        atomicAdd(&hist[u.x], 1);
        atomicAdd(&hist[u.y], 1);
        atomicAdd(&hist[u.z], 1);
        atomicAdd(&hist[u.w], 1);
    }
    __syncthreads();

    if (tid == 0) {
        int s = 0;
        for (int k = 0; k < NB; k++) { base[k] = s; s += hist[k]; }
    }
    __syncthreads();

    int myb = tid;
    int cnt = base[myb];
    unsigned short* dst = g_st + (size_t)bh * S;
    for (int i = 0; i < S; i += 4) {
        uchar4 u = *(const uchar4*)(sb + i);   // broadcast read
        if (u.x == myb) dst[cnt++] = (unsigned short)(i);
        if (u.y == myb) dst[cnt++] = (unsigned short)(i + 1);
        if (u.z == myb) dst[cnt++] = (unsigned short)(i + 2);
        if (u.w == myb) dst[cnt++] = (unsigned short)(i + 3);
    }
}

// ============================================================
// K3: GEMM-tiled bucketed attention. One 128-thread block per
// (b, chunk).  64 queries x 128 keys (chunk + prev chunk).
//
// smem (floats):
//   uA  [0..8704)      skq_t[d][key] (64x136, raw K; queries are
//                      cols 0..63) -> reused as sP_t[key][q] (128x68)
//   sv  [8704..17408)  V rows [128][68]
//   sl  [17408..18496) per-colgroup row sums [16][68]
//   srn [18496..18624) per-key 0.125/||k||
//   sinv[18624..18688) per-query 1/l
//   skid[18688..18816) key token ids (int)
// ============================================================
#define TSTRIDE 136
#define PSTRIDE 68
#define ATTN_SMEM (18816 * 4)

__global__ __launch_bounds__(128) void attn_kernel(const float* __restrict__ qk,
                                                   const float* __restrict__ vin)
{
    int b = blockIdx.y, c = blockIdx.x;
    int h = c >> 7;
    int tid = threadIdx.x;

    extern __shared__ float smem[];
    float* uA   = smem;
    float* sv   = smem + 8704;
    float* sl   = smem + 17408;
    float* srn  = smem + 18496;
    float* sinv = smem + 18624;
    int*   skid = (int*)(smem + 18688);

    const unsigned short* ST = g_st + (size_t)b * (H * S);

    // ---------------- staging: thread = key slot ----------------
    {
        int slot = tid;
        int kc = (slot < 64) ? c : ((c + CHUNKS - 1) & (CHUNKS - 1));
        int kt = ST[kc * BSZ + (slot & 63)];
        skid[slot] = kt;

        const float4* kr = (const float4*)(qk + ((size_t)b * S + kt) * D);
        float kv[64];
        float ss = 0.f;
#pragma unroll
        for (int i = 0; i < 16; i++) {
            float4 f4 = kr[i];
            kv[4*i] = f4.x; kv[4*i+1] = f4.y; kv[4*i+2] = f4.z; kv[4*i+3] = f4.w;
            ss += f4.x*f4.x + f4.y*f4.y + f4.z*f4.z + f4.w*f4.w;
        }
        srn[slot] = 0.125f / fmaxf(sqrtf(ss), 1e-12f);
#pragma unroll
        for (int d = 0; d < 64; d++) uA[d * TSTRIDE + slot] = kv[d];

        const float4* vr = (const float4*)(vin + ((size_t)b * S + kt) * D);
        float* vd = sv + slot * PSTRIDE;
#pragma unroll
        for (int i = 0; i < 16; i++) *(float4*)(vd + 4*i) = vr[i];
    }
    __syncthreads();

    // ---------------- phase 1: scores (8x8 tile per thread) ----------------
    int rg = tid & 7, cg = tid >> 3;       // 8 row-groups x 16 col-groups
    int r0 = rg * 8, c0 = cg * 8;

    ull acc[32];                           // acc[i*8+j]: rows (r0+2i, r0+2i+1), col c0+j
#pragma unroll
    for (int i = 0; i < 32; i++) acc[i] = 0ull;

    {
        const float* qp = uA + r0;
        const float* kp = uA + c0;
#pragma unroll 4
        for (int d = 0; d < 64; d++) {
            float4 qa = *(const float4*)(qp);
            float4 qb = *(const float4*)(qp + 4);
            float4 ka = *(const float4*)(kp);
            float4 kb = *(const float4*)(kp + 4);
            qp += TSTRIDE; kp += TSTRIDE;
            ull qpair[4] = { pack2(qa.x, qa.y), pack2(qa.z, qa.w),
                             pack2(qb.x, qb.y), pack2(qb.z, qb.w) };
            ull kd[8] = { pack2(ka.x, ka.x), pack2(ka.y, ka.y),
                          pack2(ka.z, ka.z), pack2(ka.w, ka.w),
                          pack2(kb.x, kb.x), pack2(kb.y, kb.y),
                          pack2(kb.z, kb.z), pack2(kb.w, kb.w) };
#pragma unroll
            for (int i = 0; i < 4; i++)
#pragma unroll
                for (int j = 0; j < 8; j++)
                    acc[i*8+j] = fma2(qpair[i], kd[j], acc[i*8+j]);
        }
    }

    // ---------------- phase 2a: scale + mask + exp (registers) ----------------
    int qt[8];
#pragma unroll
    for (int x = 0; x < 8; x++) qt[x] = skid[r0 + x];

    ull rs[4];
#pragma unroll
    for (int i = 0; i < 4; i++) rs[i] = 0ull;

#pragma unroll
    for (int j = 0; j < 8; j++) {
        int cc = c0 + j;
        float sc = srn[cc];
        int kid = skid[cc];
        ull scp = pack2(sc, sc);
#pragma unroll
        for (int i = 0; i < 4; i++) {
            ull sp = mul2(acc[i*8+j], scp);
            float slo, shi; unpack2(slo, shi, sp);
            float plo = (kid == qt[2*i])     ? 0.f : __expf(slo);
            float phi = (kid == qt[2*i + 1]) ? 0.f : __expf(shi);
            ull pp = pack2(plo, phi);
            rs[i] = add2(rs[i], pp);
            acc[i*8+j] = pp;
        }
    }
    __syncthreads();     // everyone done reading skq_t

    // ---------------- phase 2b: write P^T + row-sum partials ----------------
#pragma unroll
    for (int j = 0; j < 8; j++) {
        float* base = uA + (c0 + j) * PSTRIDE + r0;   // sP_t[key][q]
#pragma unroll
        for (int i = 0; i < 4; i++)
            *(ull*)(base + 2*i) = acc[i*8+j];
    }
    {
        float* base = sl + cg * PSTRIDE + r0;
#pragma unroll
        for (int i = 0; i < 4; i++)
            *(ull*)(base + 2*i) = rs[i];
    }
    __syncthreads();

    // ---------------- row-sum reduce + logits ----------------
    if (tid < 64) {
        float l = 0.f;
#pragma unroll
        for (int g = 0; g < 16; g++) l += sl[g * PSTRIDE + tid];
        sinv[tid] = 1.f / l;
        g_logits[((size_t)(b * H + h)) * S + skid[tid]] = __logf(l);
    }
    __syncthreads();

    // ---------------- phase 3: O = P @ V (8x4 tile per thread) ----------------
    int rg3 = tid & 7, cg3 = tid >> 3;     // 8 row-groups x 16 dim-groups
    int r3 = rg3 * 8, c3 = cg3 * 4;

    ull ao[16];                            // ao[i*4+j]: rows (r3+2i, r3+2i+1), dim c3+j
#pragma unroll
    for (int i = 0; i < 16; i++) ao[i] = 0ull;

    {
        const float* pp = uA + r3;
        const float* vp = sv + c3;
#pragma unroll 4
        for (int kk = 0; kk < 128; kk++) {
            ulonglong2 pA = *(const ulonglong2*)(pp);
            ulonglong2 pB = *(const ulonglong2*)(pp + 4);
            float4 vv = *(const float4*)(vp);
            pp += PSTRIDE; vp += PSTRIDE;
            ull pr[4] = { pA.x, pA.y, pB.x, pB.y };
            ull vd[4] = { pack2(vv.x, vv.x), pack2(vv.y, vv.y),
                          pack2(vv.z, vv.z), pack2(vv.w, vv.w) };
#pragma unroll
            for (int i = 0; i < 4; i++)
#pragma unroll
                for (int j = 0; j < 4; j++)
                    ao[i*4+j] = fma2(pr[i], vd[j], ao[i*4+j]);
        }
    }

    // ---------------- normalize + scatter-out (this is the unsort) ----------------
#pragma unroll
    for (int i = 0; i < 4; i++) {
        float ilo = sinv[r3 + 2*i], ihi = sinv[r3 + 2*i + 1];
        ull ipr = pack2(ilo, ihi);
        float o_lo[4], o_hi[4];
#pragma unroll
        for (int j = 0; j < 4; j++) {
            ull op = mul2(ao[i*4+j], ipr);
            unpack2(o_lo[j], o_hi[j], op);
        }
        int tlo = skid[r3 + 2*i], thi = skid[r3 + 2*i + 1];
        float* dlo = g_o + (((size_t)(b * H + h) * S + tlo) * D) + c3;
        float* dhi = g_o + (((size_t)(b * H + h) * S + thi) * D) + c3;
        *(float4*)dlo = make_float4(o_lo[0], o_lo[1], o_lo[2], o_lo[3]);
        *(float4*)dhi = make_float4(o_hi[0], o_hi[1], o_hi[2], o_hi[3]);
    }
}

// ============================================================
// K4: combine the H rounds with softmax(logits) weights.
// ============================================================
__global__ __launch_bounds__(256) void combine_kernel(float* __restrict__ out)
{
    int bt = blockIdx.x * 4 + (threadIdx.x >> 6);
    int b = bt >> 13, t = bt & (S - 1);
    int d = threadIdx.x & 63;

    float lg[H];
    float mx = -INFINITY;
#pragma unroll
    for (int h = 0; h < H; h++) {
        lg[h] = g_logits[((size_t)(b * H + h)) * S + t];
        mx = fmaxf(mx, lg[h]);
    }
    float sum = 0.f;
#pragma unroll
    for (int h = 0; h < H; h++) { lg[h] = __expf(lg[h] - mx); sum += lg[h]; }

    float a = 0.f;
#pragma unroll
    for (int h = 0; h < H; h++)
        a += lg[h] * g_o[(((size_t)(b * H + h)) * S + t) * D + d];

    out[((size_t)b * S + t) * D + d] = a / sum;
}

// ============================================================
extern "C" void kernel_launch(void* const* d_in, const int* in_sizes, int n_in,
                              void* d_out, int out_size)
{
    const float* qk  = (const float*)d_in[0];
    const float* v   = (const float*)d_in[1];
    const float* rot = (const float*)d_in[2];
    float* out = (float*)d_out;

    cudaFuncSetAttribute(attn_kernel, cudaFuncAttributeMaxDynamicSharedMemorySize, ATTN_SMEM);

    hash_kernel<<<dim3(32, H, B), 256>>>(qk, rot);
    sort_kernel<<<B * H, 128>>>();
    attn_kernel<<<dim3(CHUNKS, B), 128, ATTN_SMEM>>>(qk, v);
    combine_kernel<<<B * S / 4, 256>>>(out);
}

// round 6
// speedup vs baseline: 1.9062x; 1.3907x over previous
#include <cuda_runtime.h>
#include <cuda_bf16.h>
#include <math.h>

#define B 8
#define S 8192
#define D 64
#define H 8
#define NB 128
#define BSZ 64
#define CHUNKS 1024

typedef unsigned long long ull;

// ---------- packed f32x2 helpers (sm_100+) ----------
__device__ __forceinline__ ull fma2(ull a, ull b, ull c) {
    ull d; asm("fma.rn.f32x2 %0, %1, %2, %3;" : "=l"(d) : "l"(a), "l"(b), "l"(c)); return d;
}
__device__ __forceinline__ ull pack2(float x, float y) {
    ull r; asm("mov.b64 %0, {%1,%2};" : "=l"(r) : "f"(x), "f"(y)); return r;
}
__device__ __forceinline__ void unpack2(float& x, float& y, ull r) {
    asm("mov.b64 {%0,%1}, %2;" : "=f"(x), "=f"(y) : "l"(r));
}

__device__ __forceinline__ unsigned smem_u32(const void* p) {
    unsigned a; asm("{ .reg .u64 t; cvta.to.shared.u64 t, %1; cvt.u32.u64 %0, t; }" : "=r"(a) : "l"(p));
    return a;
}

// ---------- warp MMA helpers (sm_80+ baseline) ----------
__device__ __forceinline__ void ldsm4(unsigned& r0, unsigned& r1, unsigned& r2, unsigned& r3,
                                      unsigned addr) {
    asm volatile("ldmatrix.sync.aligned.m8n8.x4.shared.b16 {%0,%1,%2,%3}, [%4];"
                 : "=r"(r0), "=r"(r1), "=r"(r2), "=r"(r3) : "r"(addr));
}
__device__ __forceinline__ void mma_bf(float* c, unsigned a0, unsigned a1, unsigned a2, unsigned a3,
                                       unsigned b0, unsigned b1) {
    asm volatile("mma.sync.aligned.m16n8k16.row.col.f32.bf16.bf16.f32 "
                 "{%0,%1,%2,%3}, {%4,%5,%6,%7}, {%8,%9}, {%0,%1,%2,%3};"
                 : "+f"(c[0]), "+f"(c[1]), "+f"(c[2]), "+f"(c[3])
                 : "r"(a0), "r"(a1), "r"(a2), "r"(a3), "r"(b0), "r"(b1));
}
__device__ __forceinline__ void bsplit(float x, __nv_bfloat16& h, __nv_bfloat16& l) {
    h = __float2bfloat16(x);
    l = __float2bfloat16(x - __bfloat162float(h));
}
__device__ __forceinline__ unsigned bpair(__nv_bfloat16 a, __nv_bfloat16 b) {
    __nv_bfloat162 p; p.x = a; p.y = b;
    return *(unsigned*)&p;
}

// -------- device scratch --------
__device__ unsigned char  g_bucket[B * H * S];
__device__ unsigned short g_st[B * H * S];
__device__ float          g_logits[B * H * S];
__device__ float          g_o[(size_t)B * H * S * D];

// ============================================================
// K1: LSH hashing
// ============================================================
__global__ __launch_bounds__(256) void hash_kernel(const float* __restrict__ qk,
                                                   const float* __restrict__ rot)
{
    int b = blockIdx.z, h = blockIdx.y, tile = blockIdx.x;
    __shared__ float srot[64 * 64];
    int tid = threadIdx.x;
    for (int idx = tid; idx < 64 * 64; idx += 256) {
        int f = idx >> 6, i = idx & 63;
        srot[idx] = rot[(size_t)f * (H * 64) + h * 64 + i];
    }
    __syncthreads();

    int t = tile * 256 + tid;
    float q[64];
    const float4* qr = (const float4*)(qk + ((size_t)b * S + t) * D);
#pragma unroll
    for (int i = 0; i < 16; i++) {
        float4 f4 = qr[i];
        q[4*i] = f4.x; q[4*i+1] = f4.y; q[4*i+2] = f4.z; q[4*i+3] = f4.w;
    }

    float bestP = -INFINITY, bestN = -INFINITY;
    int ip = 0, inn = 0;
#pragma unroll
    for (int g = 0; g < 4; g++) {
        ull a2[8];
#pragma unroll
        for (int k = 0; k < 8; k++) a2[k] = 0ull;
        for (int f = 0; f < 64; f++) {
            ull qq = pack2(q[f], q[f]);
            const ulonglong2* rp = (const ulonglong2*)&srot[f * 64 + g * 16];
#pragma unroll
            for (int k = 0; k < 4; k++) {
                ulonglong2 u = rp[k];
                a2[2*k]   = fma2(qq, u.x, a2[2*k]);
                a2[2*k+1] = fma2(qq, u.y, a2[2*k+1]);
            }
        }
#pragma unroll
        for (int m = 0; m < 8; m++) {
            float lo, hi; unpack2(lo, hi, a2[m]);
            int idx = g * 16 + 4 * (m >> 1) + 2 * (m & 1);
            if (lo > bestP)  { bestP = lo;  ip  = idx;     }
            if (hi > bestP)  { bestP = hi;  ip  = idx + 1; }
            if (-lo > bestN) { bestN = -lo; inn = idx;     }
            if (-hi > bestN) { bestN = -hi; inn = idx + 1; }
        }
    }
    int bucket = (bestP >= bestN) ? ip : (64 + inn);
    g_bucket[((size_t)b * H + h) * S + t] = (unsigned char)bucket;
}

// ============================================================
// K2: stable counting sort per (b,h)
// ============================================================
__global__ __launch_bounds__(128) void sort_kernel()
{
    int bh = blockIdx.x;
    __shared__ unsigned char sb[S];
    __shared__ int hist[NB];
    __shared__ int base[NB];
    int tid = threadIdx.x;

    hist[tid] = 0;
    __syncthreads();

    const uchar4* src = (const uchar4*)(g_bucket + (size_t)bh * S);
    for (int i = tid; i < S / 4; i += 128) {
        uchar4 u = src[i];
        ((uchar4*)sb)[i] = u;
        atomicAdd(&hist[u.x], 1);
        atomicAdd(&hist[u.y], 1);
        atomicAdd(&hist[u.z], 1);
        atomicAdd(&hist[u.w], 1);
    }
    __syncthreads();

    if (tid == 0) {
        int s = 0;
        for (int k = 0; k < NB; k++) { base[k] = s; s += hist[k]; }
    }
    __syncthreads();

    int myb = tid;
    int cnt = base[myb];
    unsigned short* dst = g_st + (size_t)bh * S;
    for (int i = 0; i < S; i += 4) {
        uchar4 u = *(const uchar4*)(sb + i);
        if (u.x == myb) dst[cnt++] = (unsigned short)(i);
        if (u.y == myb) dst[cnt++] = (unsigned short)(i + 1);
        if (u.z == myb) dst[cnt++] = (unsigned short)(i + 2);
        if (u.w == myb) dst[cnt++] = (unsigned short)(i + 3);
    }
}

// ============================================================
// K3: mma.sync bf16 hi/lo 3-pass attention.
// One 128-thread block (4 warps) per (b, chunk).
// Warp w owns query rows w*16..w*16+15.
//
// smem bytes:
//   0      skid[128] (512B)
//   1024   Qhi  64x72 bf16 (9216)     [Phi aliases 1024..18432]
//   10240  Qlo  64x72 bf16 (9216)
//   19456  Khi 128x72 bf16 (18432)    [Plo aliases 19456..36864]
//   37888  Klo 128x72 bf16 (18432)
//   56320  Vthi 64x136 bf16 (17408)
//   73728  Vtlo 64x136 bf16 (17408)   -> total 91136
// ============================================================
#define SM_SKID 0
#define SM_QHI  1024
#define SM_QLO  10240
#define SM_KHI  19456
#define SM_KLO  37888
#define SM_PHI  1024
#define SM_PLO  19456
#define SM_VTHI 56320
#define SM_VTLO 73728
#define ATTN_SMEM_B 91136
#define QK_STRIDE 144     // bytes (72 bf16)
#define PV_STRIDE 272     // bytes (136 bf16)

__global__ __launch_bounds__(128) void attn_kernel(const float* __restrict__ qk,
                                                   const float* __restrict__ vin)
{
    extern __shared__ char smem[];
    unsigned sbase = smem_u32(smem);
    int tid = threadIdx.x;
    int b = blockIdx.y, c = blockIdx.x, h = c >> 7;
    int* skid = (int*)(smem + SM_SKID);

    // ---------------- staging: thread = key slot ----------------
    {
        int slot = tid;
        int kc = (slot < 64) ? c : ((c + CHUNKS - 1) & (CHUNKS - 1));
        const unsigned short* ST = g_st + (size_t)b * (H * S);
        int kt = ST[kc * BSZ + (slot & 63)];
        skid[slot] = kt;

        float kv[64];
        float ss = 0.f;
        const float4* kr = (const float4*)(qk + ((size_t)b * S + kt) * D);
#pragma unroll
        for (int i = 0; i < 16; i++) {
            float4 f4 = kr[i];
            kv[4*i] = f4.x; kv[4*i+1] = f4.y; kv[4*i+2] = f4.z; kv[4*i+3] = f4.w;
            ss += f4.x*f4.x + f4.y*f4.y + f4.z*f4.z + f4.w*f4.w;
        }
        float rn = 0.125f / fmaxf(sqrtf(ss), 1e-12f);

#pragma unroll
        for (int g = 0; g < 8; g++) {
            uint4 hi4, lo4;
            unsigned* hw = (unsigned*)&hi4;
            unsigned* lw = (unsigned*)&lo4;
#pragma unroll
            for (int e = 0; e < 4; e++) {
                __nv_bfloat16 h0, l0, h1, l1;
                bsplit(kv[g*8 + 2*e]     * rn, h0, l0);
                bsplit(kv[g*8 + 2*e + 1] * rn, h1, l1);
                hw[e] = bpair(h0, h1); lw[e] = bpair(l0, l1);
            }
            *(uint4*)(smem + SM_KHI + slot * QK_STRIDE + g * 16) = hi4;
            *(uint4*)(smem + SM_KLO + slot * QK_STRIDE + g * 16) = lo4;
            if (slot < 64) {
#pragma unroll
                for (int e = 0; e < 4; e++) {
                    __nv_bfloat16 h0, l0, h1, l1;
                    bsplit(kv[g*8 + 2*e],     h0, l0);
                    bsplit(kv[g*8 + 2*e + 1], h1, l1);
                    hw[e] = bpair(h0, h1); lw[e] = bpair(l0, l1);
                }
                *(uint4*)(smem + SM_QHI + slot * QK_STRIDE + g * 16) = hi4;
                *(uint4*)(smem + SM_QLO + slot * QK_STRIDE + g * 16) = lo4;
            }
        }

        // V^T: Vt[d][key=slot], bf16 hi/lo
        const float4* vr = (const float4*)(vin + ((size_t)b * S + kt) * D);
#pragma unroll
        for (int i = 0; i < 16; i++) {
            float4 f4 = vr[i];
            float vv[4] = { f4.x, f4.y, f4.z, f4.w };
#pragma unroll
            for (int e = 0; e < 4; e++) {
                int d = 4*i + e;
                __nv_bfloat16 hb, lb;
                bsplit(vv[e], hb, lb);
                *(__nv_bfloat16*)(smem + SM_VTHI + d * PV_STRIDE + slot * 2) = hb;
                *(__nv_bfloat16*)(smem + SM_VTLO + d * PV_STRIDE + slot * 2) = lb;
            }
        }
    }
    __syncthreads();

    int lane = tid & 31, warp = tid >> 5;
    int wr = warp * 16;
    int g = lane >> 2, tg = lane & 3;

    unsigned aRowOff = (unsigned)((wr + (lane & 15)) * QK_STRIDE + (lane >> 4) * 16);
    unsigned bn  = (lane & 7) + ((lane >> 4) << 3);
    unsigned bkh = (lane >> 3) & 1;

    // ---------------- MMA1: S = Q K^T, 3 passes ----------------
    float cS[64];
#pragma unroll
    for (int i = 0; i < 64; i++) cS[i] = 0.f;

#pragma unroll
    for (int ks = 0; ks < 4; ks++) {
        unsigned aaddr = sbase + SM_QHI + aRowOff + ks * 32;
        unsigned aH0, aH1, aH2, aH3, aL0, aL1, aL2, aL3;
        ldsm4(aH0, aH1, aH2, aH3, aaddr);
        ldsm4(aL0, aL1, aL2, aL3, aaddr + (SM_QLO - SM_QHI));
#pragma unroll
        for (int jp = 0; jp < 8; jp++) {
            unsigned baddr = sbase + SM_KHI + (jp * 16 + bn) * QK_STRIDE + bkh * 16 + ks * 32;
            unsigned bH0, bH1, bH2, bH3, bL0, bL1, bL2, bL3;
            ldsm4(bH0, bH1, bH2, bH3, baddr);
            ldsm4(bL0, bL1, bL2, bL3, baddr + (SM_KLO - SM_KHI));
            float* c0 = cS + (2*jp) * 4;
            float* c1 = cS + (2*jp + 1) * 4;
            mma_bf(c0, aH0, aH1, aH2, aH3, bH0, bH1);
            mma_bf(c0, aL0, aL1, aL2, aL3, bH0, bH1);
            mma_bf(c0, aH0, aH1, aH2, aH3, bL0, bL1);
            mma_bf(c1, aH0, aH1, aH2, aH3, bH2, bH3);
            mma_bf(c1, aL0, aL1, aL2, aL3, bH2, bH3);
            mma_bf(c1, aH0, aH1, aH2, aH3, bL2, bL3);
        }
    }

    // ---------------- epilogue: mask + exp + P split ----------------
    int r1 = wr + g, r2 = r1 + 8;
    int tok1 = skid[r1], tok2 = skid[r2];
    float l1 = 0.f, l2 = 0.f;

    __syncthreads();   // all warps done reading Q/K before P overwrites them

#pragma unroll
    for (int j = 0; j < 16; j++) {
        int jc = j * 8 + tg * 2;
        int kid0 = skid[jc], kid1 = skid[jc + 1];
        float p00 = (kid0 == tok1) ? 0.f : __expf(cS[j*4 + 0]);
        float p01 = (kid1 == tok1) ? 0.f : __expf(cS[j*4 + 1]);
        float p10 = (kid0 == tok2) ? 0.f : __expf(cS[j*4 + 2]);
        float p11 = (kid1 == tok2) ? 0.f : __expf(cS[j*4 + 3]);
        l1 += p00 + p01;
        l2 += p10 + p11;
        __nv_bfloat16 ha, la, hb, lb;
        bsplit(p00, ha, la); bsplit(p01, hb, lb);
        *(unsigned*)(smem + SM_PHI + r1 * PV_STRIDE + jc * 2) = bpair(ha, hb);
        *(unsigned*)(smem + SM_PLO + r1 * PV_STRIDE + jc * 2) = bpair(la, lb);
        bsplit(p10, ha, la); bsplit(p11, hb, lb);
        *(unsigned*)(smem + SM_PHI + r2 * PV_STRIDE + jc * 2) = bpair(ha, hb);
        *(unsigned*)(smem + SM_PLO + r2 * PV_STRIDE + jc * 2) = bpair(la, lb);
    }

    l1 += __shfl_xor_sync(0xffffffffu, l1, 1);
    l1 += __shfl_xor_sync(0xffffffffu, l1, 2);
    l2 += __shfl_xor_sync(0xffffffffu, l2, 1);
    l2 += __shfl_xor_sync(0xffffffffu, l2, 2);
    float linv1 = 1.f / l1, linv2 = 1.f / l2;
    if (tg == 0) {
        size_t lbase = (size_t)(b * H + h) * S;
        g_logits[lbase + tok1] = __logf(l1);
        g_logits[lbase + tok2] = __logf(l2);
    }
    __syncwarp();      // P stores visible to own-warp ldmatrix (A reads own rows only)

    // ---------------- MMA2: O = P V, 3 passes ----------------
    float oacc[32];
#pragma unroll
    for (int i = 0; i < 32; i++) oacc[i] = 0.f;

    unsigned a2RowOff = (unsigned)((wr + (lane & 15)) * PV_STRIDE + (lane >> 4) * 16);
#pragma unroll
    for (int ks = 0; ks < 8; ks++) {
        unsigned aaddr = sbase + SM_PHI + a2RowOff + ks * 32;
        unsigned pH0, pH1, pH2, pH3, pL0, pL1, pL2, pL3;
        ldsm4(pH0, pH1, pH2, pH3, aaddr);
        ldsm4(pL0, pL1, pL2, pL3, aaddr + (SM_PLO - SM_PHI));
#pragma unroll
        for (int jp = 0; jp < 4; jp++) {
            unsigned baddr = sbase + SM_VTHI + (jp * 16 + bn) * PV_STRIDE + bkh * 16 + ks * 32;
            unsigned vH0, vH1, vH2, vH3, vL0, vL1, vL2, vL3;
            ldsm4(vH0, vH1, vH2, vH3, baddr);
            ldsm4(vL0, vL1, vL2, vL3, baddr + (SM_VTLO - SM_VTHI));
            float* o0 = oacc + (2*jp) * 4;
            float* o1 = oacc + (2*jp + 1) * 4;
            mma_bf(o0, pH0, pH1, pH2, pH3, vH0, vH1);
            mma_bf(o0, pL0, pL1, pL2, pL3, vH0, vH1);
            mma_bf(o0, pH0, pH1, pH2, pH3, vL0, vL1);
            mma_bf(o1, pH0, pH1, pH2, pH3, vH2, vH3);
            mma_bf(o1, pL0, pL1, pL2, pL3, vH2, vH3);
            mma_bf(o1, pH0, pH1, pH2, pH3, vL2, vL3);
        }
    }

    // ---------------- normalize + scatter (the unsort) ----------------
    float* orow1 = g_o + (((size_t)(b * H + h) * S + tok1) * D);
    float* orow2 = g_o + (((size_t)(b * H + h) * S + tok2) * D);
#pragma unroll
    for (int j = 0; j < 8; j++) {
        int col = j * 8 + tg * 2;
        float2 w1 = make_float2(oacc[j*4 + 0] * linv1, oacc[j*4 + 1] * linv1);
        float2 w2 = make_float2(oacc[j*4 + 2] * linv2, oacc[j*4 + 3] * linv2);
        *(float2*)(orow1 + col) = w1;
        *(float2*)(orow2 + col) = w2;
    }
}

// ============================================================
// K4: combine the H rounds with softmax(logits) weights.
// ============================================================
__global__ __launch_bounds__(256) void combine_kernel(float* __restrict__ out)
{
    int bt = blockIdx.x * 4 + (threadIdx.x >> 6);
    int b = bt >> 13, t = bt & (S - 1);
    int d = threadIdx.x & 63;

    float lg[H];
    float mx = -INFINITY;
#pragma unroll
    for (int h = 0; h < H; h++) {
        lg[h] = g_logits[((size_t)(b * H + h)) * S + t];
        mx = fmaxf(mx, lg[h]);
    }
    float sum = 0.f;
#pragma unroll
    for (int h = 0; h < H; h++) { lg[h] = __expf(lg[h] - mx); sum += lg[h]; }

    float a = 0.f;
#pragma unroll
    for (int h = 0; h < H; h++)
        a += lg[h] * g_o[(((size_t)(b * H + h)) * S + t) * D + d];

    out[((size_t)b * S + t) * D + d] = a / sum;
}

// ============================================================
extern "C" void kernel_launch(void* const* d_in, const int* in_sizes, int n_in,
                              void* d_out, int out_size)
{
    const float* qk  = (const float*)d_in[0];
    const float* v   = (const float*)d_in[1];
    const float* rot = (const float*)d_in[2];
    float* out = (float*)d_out;

    cudaFuncSetAttribute(attn_kernel, cudaFuncAttributeMaxDynamicSharedMemorySize, ATTN_SMEM_B);

    hash_kernel<<<dim3(32, H, B), 256>>>(qk, rot);
    sort_kernel<<<B * H, 128>>>();
    attn_kernel<<<dim3(CHUNKS, B), 128, ATTN_SMEM_B>>>(qk, v);
    combine_kernel<<<B * S / 4, 256>>>(out);
}

// round 7
// speedup vs baseline: 2.1481x; 1.1269x over previous
#include <cuda_runtime.h>
#include <cuda_bf16.h>
#include <math.h>

#define B 8
#define S 8192
#define D 64
#define H 8
#define NB 128
#define BSZ 64
#define CHUNKS 1024

typedef unsigned long long ull;

// ---------- packed f32x2 helpers (sm_100+) ----------
__device__ __forceinline__ ull fma2(ull a, ull b, ull c) {
    ull d; asm("fma.rn.f32x2 %0, %1, %2, %3;" : "=l"(d) : "l"(a), "l"(b), "l"(c)); return d;
}
__device__ __forceinline__ ull pack2(float x, float y) {
    ull r; asm("mov.b64 %0, {%1,%2};" : "=l"(r) : "f"(x), "f"(y)); return r;
}
__device__ __forceinline__ void unpack2(float& x, float& y, ull r) {
    asm("mov.b64 {%0,%1}, %2;" : "=f"(x), "=f"(y) : "l"(r));
}

__device__ __forceinline__ unsigned smem_u32(const void* p) {
    unsigned a; asm("{ .reg .u64 t; cvta.to.shared.u64 t, %1; cvt.u32.u64 %0, t; }" : "=r"(a) : "l"(p));
    return a;
}

// ---------- warp MMA helpers (sm_80+ baseline) ----------
__device__ __forceinline__ void ldsm4(unsigned& r0, unsigned& r1, unsigned& r2, unsigned& r3,
                                      unsigned addr) {
    asm volatile("ldmatrix.sync.aligned.m8n8.x4.shared.b16 {%0,%1,%2,%3}, [%4];"
                 : "=r"(r0), "=r"(r1), "=r"(r2), "=r"(r3) : "r"(addr));
}
__device__ __forceinline__ void ldsm4t(unsigned& r0, unsigned& r1, unsigned& r2, unsigned& r3,
                                       unsigned addr) {
    asm volatile("ldmatrix.sync.aligned.m8n8.x4.trans.shared.b16 {%0,%1,%2,%3}, [%4];"
                 : "=r"(r0), "=r"(r1), "=r"(r2), "=r"(r3) : "r"(addr));
}
__device__ __forceinline__ void mma_bf(float* c, unsigned a0, unsigned a1, unsigned a2, unsigned a3,
                                       unsigned b0, unsigned b1) {
    asm volatile("mma.sync.aligned.m16n8k16.row.col.f32.bf16.bf16.f32 "
                 "{%0,%1,%2,%3}, {%4,%5,%6,%7}, {%8,%9}, {%0,%1,%2,%3};"
                 : "+f"(c[0]), "+f"(c[1]), "+f"(c[2]), "+f"(c[3])
                 : "r"(a0), "r"(a1), "r"(a2), "r"(a3), "r"(b0), "r"(b1));
}
__device__ __forceinline__ void bsplit(float x, __nv_bfloat16& h, __nv_bfloat16& l) {
    h = __float2bfloat16(x);
    l = __float2bfloat16(x - __bfloat162float(h));
}
__device__ __forceinline__ unsigned bpair(__nv_bfloat16 a, __nv_bfloat16 b) {
    __nv_bfloat162 p; p.x = a; p.y = b;
    return *(unsigned*)&p;
}

// -------- device scratch --------
__device__ unsigned char  g_bucket[B * H * S];
__device__ unsigned short g_st[B * H * S];
__device__ float          g_logits[B * H * S];
__device__ float          g_o[(size_t)B * H * S * D];

// ============================================================
// K1: LSH hashing
// ============================================================
__global__ __launch_bounds__(256) void hash_kernel(const float* __restrict__ qk,
                                                   const float* __restrict__ rot)
{
    int b = blockIdx.z, h = blockIdx.y, tile = blockIdx.x;
    __shared__ float srot[64 * 64];
    int tid = threadIdx.x;
    for (int idx = tid; idx < 64 * 64; idx += 256) {
        int f = idx >> 6, i = idx & 63;
        srot[idx] = rot[(size_t)f * (H * 64) + h * 64 + i];
    }
    __syncthreads();

    int t = tile * 256 + tid;
    float q[64];
    const float4* qr = (const float4*)(qk + ((size_t)b * S + t) * D);
#pragma unroll
    for (int i = 0; i < 16; i++) {
        float4 f4 = qr[i];
        q[4*i] = f4.x; q[4*i+1] = f4.y; q[4*i+2] = f4.z; q[4*i+3] = f4.w;
    }

    float bestP = -INFINITY, bestN = -INFINITY;
    int ip = 0, inn = 0;
#pragma unroll
    for (int g = 0; g < 4; g++) {
        ull a2[8];
#pragma unroll
        for (int k = 0; k < 8; k++) a2[k] = 0ull;
        for (int f = 0; f < 64; f++) {
            ull qq = pack2(q[f], q[f]);
            const ulonglong2* rp = (const ulonglong2*)&srot[f * 64 + g * 16];
#pragma unroll
            for (int k = 0; k < 4; k++) {
                ulonglong2 u = rp[k];
                a2[2*k]   = fma2(qq, u.x, a2[2*k]);
                a2[2*k+1] = fma2(qq, u.y, a2[2*k+1]);
            }
        }
#pragma unroll
        for (int m = 0; m < 8; m++) {
            float lo, hi; unpack2(lo, hi, a2[m]);
            int idx = g * 16 + 4 * (m >> 1) + 2 * (m & 1);
            if (lo > bestP)  { bestP = lo;  ip  = idx;     }
            if (hi > bestP)  { bestP = hi;  ip  = idx + 1; }
            if (-lo > bestN) { bestN = -lo; inn = idx;     }
            if (-hi > bestN) { bestN = -hi; inn = idx + 1; }
        }
    }
    int bucket = (bestP >= bestN) ? ip : (64 + inn);
    g_bucket[((size_t)b * H + h) * S + t] = (unsigned char)bucket;
}

// ============================================================
// K2: stable counting sort per (b,h)
// ============================================================
__global__ __launch_bounds__(128) void sort_kernel()
{
    int bh = blockIdx.x;
    __shared__ unsigned char sb[S];
    __shared__ int hist[NB];
    __shared__ int base[NB];
    int tid = threadIdx.x;

    hist[tid] = 0;
    __syncthreads();

    const uchar4* src = (const uchar4*)(g_bucket + (size_t)bh * S);
    for (int i = tid; i < S / 4; i += 128) {
        uchar4 u = src[i];
        ((uchar4*)sb)[i] = u;
        atomicAdd(&hist[u.x], 1);
        atomicAdd(&hist[u.y], 1);
        atomicAdd(&hist[u.z], 1);
        atomicAdd(&hist[u.w], 1);
    }
    __syncthreads();

    if (tid == 0) {
        int s = 0;
        for (int k = 0; k < NB; k++) { base[k] = s; s += hist[k]; }
    }
    __syncthreads();

    int myb = tid;
    int cnt = base[myb];
    unsigned short* dst = g_st + (size_t)bh * S;
    for (int i = 0; i < S; i += 4) {
        uchar4 u = *(const uchar4*)(sb + i);
        if (u.x == myb) dst[cnt++] = (unsigned short)(i);
        if (u.y == myb) dst[cnt++] = (unsigned short)(i + 1);
        if (u.z == myb) dst[cnt++] = (unsigned short)(i + 2);
        if (u.w == myb) dst[cnt++] = (unsigned short)(i + 3);
    }
}

// ============================================================
// K3: mma.sync bf16 hi/lo 3-pass attention, v2.
//  - single raw KQ tile (queries = rows 0..63); per-key scale
//    srn folded into the epilogue (exact fp32 mult)
//  - V row-major hi/lo, MMA2 B fragments via ldmatrix.trans
//  - smem 73KB -> 3 CTAs/SM
//
// smem bytes:
//   0      skid[128]            512   srn[128]
//   1024   KQhi 128x72 (18432)  [Phi aliases 1024..18432]
//   19456  KQlo 128x72 (18432)  [Plo aliases 18432..35840]
//   37888  Vhi 128x72 (18432)
//   56320  Vlo 128x72 (18432)   -> total 74752
// ============================================================
#define SM_SKID 0
#define SM_SRN  512
#define SM_KQHI 1024
#define SM_KQLO 19456
#define SM_PHI  1024
#define SM_PLO  18432
#define SM_VHI  37888
#define SM_VLO  56320
#define ATTN_SMEM_B 74752
#define KQ_STRIDE 144     // bytes (72 bf16)
#define P_STRIDE  272     // bytes (136 bf16)

__global__ __launch_bounds__(128) void attn_kernel(const float* __restrict__ qk,
                                                   const float* __restrict__ vin)
{
    extern __shared__ char smem[];
    unsigned sbase = smem_u32(smem);
    int tid = threadIdx.x;
    int b = blockIdx.y, c = blockIdx.x, h = c >> 7;
    int* skid = (int*)(smem + SM_SKID);
    float* srn_s = (float*)(smem + SM_SRN);

    // ---------------- staging: thread = key slot ----------------
    {
        int slot = tid;
        int kc = (slot < 64) ? c : ((c + CHUNKS - 1) & (CHUNKS - 1));
        const unsigned short* ST = g_st + (size_t)b * (H * S);
        int kt = ST[kc * BSZ + (slot & 63)];
        skid[slot] = kt;

        float kv[64];
        float ss = 0.f;
        const float4* kr = (const float4*)(qk + ((size_t)b * S + kt) * D);
#pragma unroll
        for (int i = 0; i < 16; i++) {
            float4 f4 = kr[i];
            kv[4*i] = f4.x; kv[4*i+1] = f4.y; kv[4*i+2] = f4.z; kv[4*i+3] = f4.w;
            ss += f4.x*f4.x + f4.y*f4.y + f4.z*f4.z + f4.w*f4.w;
        }
        srn_s[slot] = 0.125f / fmaxf(sqrtf(ss), 1e-12f);

        // raw KQ rows (hi/lo)
#pragma unroll
        for (int g = 0; g < 8; g++) {
            uint4 hi4, lo4;
            unsigned* hw = (unsigned*)&hi4;
            unsigned* lw = (unsigned*)&lo4;
#pragma unroll
            for (int e = 0; e < 4; e++) {
                __nv_bfloat16 h0, l0, h1, l1;
                bsplit(kv[g*8 + 2*e],     h0, l0);
                bsplit(kv[g*8 + 2*e + 1], h1, l1);
                hw[e] = bpair(h0, h1); lw[e] = bpair(l0, l1);
            }
            *(uint4*)(smem + SM_KQHI + slot * KQ_STRIDE + g * 16) = hi4;
            *(uint4*)(smem + SM_KQLO + slot * KQ_STRIDE + g * 16) = lo4;
        }

        // V rows (hi/lo), row-major — MMA2 uses ldmatrix.trans
        const float4* vr = (const float4*)(vin + ((size_t)b * S + kt) * D);
        float vv[64];
#pragma unroll
        for (int i = 0; i < 16; i++) {
            float4 f4 = vr[i];
            vv[4*i] = f4.x; vv[4*i+1] = f4.y; vv[4*i+2] = f4.z; vv[4*i+3] = f4.w;
        }
#pragma unroll
        for (int g = 0; g < 8; g++) {
            uint4 hi4, lo4;
            unsigned* hw = (unsigned*)&hi4;
            unsigned* lw = (unsigned*)&lo4;
#pragma unroll
            for (int e = 0; e < 4; e++) {
                __nv_bfloat16 h0, l0, h1, l1;
                bsplit(vv[g*8 + 2*e],     h0, l0);
                bsplit(vv[g*8 + 2*e + 1], h1, l1);
                hw[e] = bpair(h0, h1); lw[e] = bpair(l0, l1);
            }
            *(uint4*)(smem + SM_VHI + slot * KQ_STRIDE + g * 16) = hi4;
            *(uint4*)(smem + SM_VLO + slot * KQ_STRIDE + g * 16) = lo4;
        }
    }
    __syncthreads();

    int lane = tid & 31, warp = tid >> 5;
    int wr = warp * 16;
    int g = lane >> 2, tg = lane & 3;

    unsigned aRowOff = (unsigned)((wr + (lane & 15)) * KQ_STRIDE + (lane >> 4) * 16);
    unsigned bn  = (lane & 7) + ((lane >> 4) << 3);
    unsigned bkh = (lane >> 3) & 1;

    // ---------------- MMA1: S_raw = Q_raw K_raw^T, 3 passes ----------------
    float cS[64];
#pragma unroll
    for (int i = 0; i < 64; i++) cS[i] = 0.f;

#pragma unroll
    for (int ks = 0; ks < 4; ks++) {
        unsigned aaddr = sbase + SM_KQHI + aRowOff + ks * 32;
        unsigned aH0, aH1, aH2, aH3, aL0, aL1, aL2, aL3;
        ldsm4(aH0, aH1, aH2, aH3, aaddr);
        ldsm4(aL0, aL1, aL2, aL3, aaddr + (SM_KQLO - SM_KQHI));
#pragma unroll
        for (int jp = 0; jp < 8; jp++) {
            unsigned baddr = sbase + SM_KQHI + (jp * 16 + bn) * KQ_STRIDE + bkh * 16 + ks * 32;
            unsigned bH0, bH1, bH2, bH3, bL0, bL1, bL2, bL3;
            ldsm4(bH0, bH1, bH2, bH3, baddr);
            ldsm4(bL0, bL1, bL2, bL3, baddr + (SM_KQLO - SM_KQHI));
            float* c0 = cS + (2*jp) * 4;
            float* c1 = cS + (2*jp + 1) * 4;
            mma_bf(c0, aH0, aH1, aH2, aH3, bH0, bH1);
            mma_bf(c0, aL0, aL1, aL2, aL3, bH0, bH1);
            mma_bf(c0, aH0, aH1, aH2, aH3, bL0, bL1);
            mma_bf(c1, aH0, aH1, aH2, aH3, bH2, bH3);
            mma_bf(c1, aL0, aL1, aL2, aL3, bH2, bH3);
            mma_bf(c1, aH0, aH1, aH2, aH3, bL2, bL3);
        }
    }

    // ---------------- epilogue: scale + mask + exp + P split ----------------
    int r1 = wr + g, r2 = r1 + 8;
    int tok1 = skid[r1], tok2 = skid[r2];
    float l1 = 0.f, l2 = 0.f;

    __syncthreads();   // all warps done reading KQ before P overwrites it

#pragma unroll
    for (int j = 0; j < 16; j++) {
        int jc = j * 8 + tg * 2;
        int kid0 = skid[jc], kid1 = skid[jc + 1];
        float sc0 = srn_s[jc], sc1 = srn_s[jc + 1];
        float p00 = (kid0 == tok1) ? 0.f : __expf(cS[j*4 + 0] * sc0);
        float p01 = (kid1 == tok1) ? 0.f : __expf(cS[j*4 + 1] * sc1);
        float p10 = (kid0 == tok2) ? 0.f : __expf(cS[j*4 + 2] * sc0);
        float p11 = (kid1 == tok2) ? 0.f : __expf(cS[j*4 + 3] * sc1);
        l1 += p00 + p01;
        l2 += p10 + p11;
        __nv_bfloat16 ha, la, hb, lb;
        bsplit(p00, ha, la); bsplit(p01, hb, lb);
        *(unsigned*)(smem + SM_PHI + r1 * P_STRIDE + jc * 2) = bpair(ha, hb);
        *(unsigned*)(smem + SM_PLO + r1 * P_STRIDE + jc * 2) = bpair(la, lb);
        bsplit(p10, ha, la); bsplit(p11, hb, lb);
        *(unsigned*)(smem + SM_PHI + r2 * P_STRIDE + jc * 2) = bpair(ha, hb);
        *(unsigned*)(smem + SM_PLO + r2 * P_STRIDE + jc * 2) = bpair(la, lb);
    }

    l1 += __shfl_xor_sync(0xffffffffu, l1, 1);
    l1 += __shfl_xor_sync(0xffffffffu, l1, 2);
    l2 += __shfl_xor_sync(0xffffffffu, l2, 1);
    l2 += __shfl_xor_sync(0xffffffffu, l2, 2);
    float linv1 = 1.f / l1, linv2 = 1.f / l2;
    if (tg == 0) {
        size_t lbase = (size_t)(b * H + h) * S;
        g_logits[lbase + tok1] = __logf(l1);
        g_logits[lbase + tok2] = __logf(l2);
    }
    __syncwarp();      // P stores visible to own-warp ldmatrix (A reads own rows only)

    // ---------------- MMA2: O = P V, 3 passes ----------------
    float oacc[32];
#pragma unroll
    for (int i = 0; i < 32; i++) oacc[i] = 0.f;

    unsigned a2RowOff = (unsigned)((wr + (lane & 15)) * P_STRIDE + (lane >> 4) * 16);
    unsigned vRow = lane & 15, vColHalf = lane >> 4;
#pragma unroll
    for (int ks = 0; ks < 8; ks++) {
        unsigned aaddr = sbase + SM_PHI + a2RowOff + ks * 32;
        unsigned pH0, pH1, pH2, pH3, pL0, pL1, pL2, pL3;
        ldsm4(pH0, pH1, pH2, pH3, aaddr);
        ldsm4(pL0, pL1, pL2, pL3, aaddr + (SM_PLO - SM_PHI));
#pragma unroll
        for (int jp = 0; jp < 4; jp++) {
            unsigned baddr = sbase + SM_VHI + (ks * 16 + vRow) * KQ_STRIDE + vColHalf * 16 + jp * 32;
            unsigned vH0, vH1, vH2, vH3, vL0, vL1, vL2, vL3;
            ldsm4t(vH0, vH1, vH2, vH3, baddr);
            ldsm4t(vL0, vL1, vL2, vL3, baddr + (SM_VLO - SM_VHI));
            float* o0 = oacc + (2*jp) * 4;
            float* o1 = oacc + (2*jp + 1) * 4;
            mma_bf(o0, pH0, pH1, pH2, pH3, vH0, vH1);
            mma_bf(o0, pL0, pL1, pL2, pL3, vH0, vH1);
            mma_bf(o0, pH0, pH1, pH2, pH3, vL0, vL1);
            mma_bf(o1, pH0, pH1, pH2, pH3, vH2, vH3);
            mma_bf(o1, pL0, pL1, pL2, pL3, vH2, vH3);
            mma_bf(o1, pH0, pH1, pH2, pH3, vL2, vL3);
        }
    }

    // ---------------- normalize + scatter (the unsort) ----------------
    float* orow1 = g_o + (((size_t)(b * H + h) * S + tok1) * D);
    float* orow2 = g_o + (((size_t)(b * H + h) * S + tok2) * D);
#pragma unroll
    for (int j = 0; j < 8; j++) {
        int col = j * 8 + tg * 2;
        float2 w1 = make_float2(oacc[j*4 + 0] * linv1, oacc[j*4 + 1] * linv1);
        float2 w2 = make_float2(oacc[j*4 + 2] * linv2, oacc[j*4 + 3] * linv2);
        *(float2*)(orow1 + col) = w1;
        *(float2*)(orow2 + col) = w2;
    }
}

// ============================================================
// K4: combine the H rounds with softmax(logits) weights.
// ============================================================
__global__ __launch_bounds__(256) void combine_kernel(float* __restrict__ out)
{
    int bt = blockIdx.x * 4 + (threadIdx.x >> 6);
    int b = bt >> 13, t = bt & (S - 1);
    int d = threadIdx.x & 63;

    float lg[H];
    float mx = -INFINITY;
#pragma unroll
    for (int h = 0; h < H; h++) {
        lg[h] = g_logits[((size_t)(b * H + h)) * S + t];
        mx = fmaxf(mx, lg[h]);
    }
    float sum = 0.f;
#pragma unroll
    for (int h = 0; h < H; h++) { lg[h] = __expf(lg[h] - mx); sum += lg[h]; }

    float a = 0.f;
#pragma unroll
    for (int h = 0; h < H; h++)
        a += lg[h] * g_o[(((size_t)(b * H + h)) * S + t) * D + d];

    out[((size_t)b * S + t) * D + d] = a / sum;
}

// ============================================================
extern "C" void kernel_launch(void* const* d_in, const int* in_sizes, int n_in,
                              void* d_out, int out_size)
{
    const float* qk  = (const float*)d_in[0];
    const float* v   = (const float*)d_in[1];
    const float* rot = (const float*)d_in[2];
    float* out = (float*)d_out;

    cudaFuncSetAttribute(attn_kernel, cudaFuncAttributeMaxDynamicSharedMemorySize, ATTN_SMEM_B);

    hash_kernel<<<dim3(32, H, B), 256>>>(qk, rot);
    sort_kernel<<<B * H, 128>>>();
    attn_kernel<<<dim3(CHUNKS, B), 128, ATTN_SMEM_B>>>(qk, v);
    combine_kernel<<<B * S / 4, 256>>>(out);
}

// round 8
// speedup vs baseline: 2.5347x; 1.1800x over previous
#include <cuda_runtime.h>
#include <cuda_bf16.h>
#include <cuda_fp16.h>
#include <math.h>

#define B 8
#define S 8192
#define D 64
#define H 8
#define NB 128
#define BSZ 64
#define CHUNKS 1024

typedef unsigned long long ull;

// ---------- packed f32x2 helpers (sm_100+) ----------
__device__ __forceinline__ ull fma2(ull a, ull b, ull c) {
    ull d; asm("fma.rn.f32x2 %0, %1, %2, %3;" : "=l"(d) : "l"(a), "l"(b), "l"(c)); return d;
}
__device__ __forceinline__ ull pack2(float x, float y) {
    ull r; asm("mov.b64 %0, {%1,%2};" : "=l"(r) : "f"(x), "f"(y)); return r;
}
__device__ __forceinline__ void unpack2(float& x, float& y, ull r) {
    asm("mov.b64 {%0,%1}, %2;" : "=f"(x), "=f"(y) : "l"(r));
}

__device__ __forceinline__ unsigned smem_u32(const void* p) {
    unsigned a; asm("{ .reg .u64 t; cvta.to.shared.u64 t, %1; cvt.u32.u64 %0, t; }" : "=r"(a) : "l"(p));
    return a;
}

// ---------- warp MMA helpers (sm_80+ baseline) ----------
__device__ __forceinline__ void ldsm4(unsigned& r0, unsigned& r1, unsigned& r2, unsigned& r3,
                                      unsigned addr) {
    asm volatile("ldmatrix.sync.aligned.m8n8.x4.shared.b16 {%0,%1,%2,%3}, [%4];"
                 : "=r"(r0), "=r"(r1), "=r"(r2), "=r"(r3) : "r"(addr));
}
__device__ __forceinline__ void ldsm4t(unsigned& r0, unsigned& r1, unsigned& r2, unsigned& r3,
                                       unsigned addr) {
    asm volatile("ldmatrix.sync.aligned.m8n8.x4.trans.shared.b16 {%0,%1,%2,%3}, [%4];"
                 : "=r"(r0), "=r"(r1), "=r"(r2), "=r"(r3) : "r"(addr));
}
__device__ __forceinline__ void mma_bf(float* c, unsigned a0, unsigned a1, unsigned a2, unsigned a3,
                                       unsigned b0, unsigned b1) {
    asm volatile("mma.sync.aligned.m16n8k16.row.col.f32.bf16.bf16.f32 "
                 "{%0,%1,%2,%3}, {%4,%5,%6,%7}, {%8,%9}, {%0,%1,%2,%3};"
                 : "+f"(c[0]), "+f"(c[1]), "+f"(c[2]), "+f"(c[3])
                 : "r"(a0), "r"(a1), "r"(a2), "r"(a3), "r"(b0), "r"(b1));
}
__device__ __forceinline__ void mma_fp16(float* c, unsigned a0, unsigned a1, unsigned a2, unsigned a3,
                                         unsigned b0, unsigned b1) {
    asm volatile("mma.sync.aligned.m16n8k16.row.col.f32.f16.f16.f32 "
                 "{%0,%1,%2,%3}, {%4,%5,%6,%7}, {%8,%9}, {%0,%1,%2,%3};"
                 : "+f"(c[0]), "+f"(c[1]), "+f"(c[2]), "+f"(c[3])
                 : "r"(a0), "r"(a1), "r"(a2), "r"(a3), "r"(b0), "r"(b1));
}
__device__ __forceinline__ void bsplit(float x, __nv_bfloat16& h, __nv_bfloat16& l) {
    h = __float2bfloat16(x);
    l = __float2bfloat16(x - __bfloat162float(h));
}
__device__ __forceinline__ unsigned bpair(__nv_bfloat16 a, __nv_bfloat16 b) {
    __nv_bfloat162 p; p.x = a; p.y = b;
    return *(unsigned*)&p;
}
__device__ __forceinline__ unsigned hpair(__half a, __half b) {
    __half2 p; p.x = a; p.y = b;
    return *(unsigned*)&p;
}

// -------- device scratch --------
__device__ unsigned char  g_bucket[B * H * S];
__device__ unsigned short g_st[B * H * S];
__device__ float          g_logits[B * H * S];
__device__ float          g_o[(size_t)B * H * S * D];

// ============================================================
// K1: LSH hashing, v2.  128 threads/block, 128 tokens/block.
// q staged TRANSPOSED in smem; warp = 16-output group; thread =
// 4 tokens.  Per f: 4 broadcast rot LDS.128 + 1 q LDS.128 ->
// 32 fma2 (FMA:LDS = 6.4:1).  fp32 exact (argmax stability).
//
// dyn smem (bytes):
//   0      srot 64x64 f32        (16384)
//   16384  sqT  64x132 f32       (33792)   sq[f][tok], pad 4
//   50176  sPv  4x128 f32        (2048)
//   52224  sNv  4x128 f32        (2048)
//   54272  sPi  4x128 i32        (2048)
//   56320  sNi  4x128 i32        (2048)    total 58368
// ============================================================
#define HQ_STRIDE 132
#define HASH_SMEM_B 58368

__global__ __launch_bounds__(128) void hash_kernel(const float* __restrict__ qk,
                                                   const float* __restrict__ rot)
{
    extern __shared__ float hsm[];
    float* srot = hsm;                    // [f*64 + i]
    float* sqT  = hsm + 4096;             // [f*132 + tok]
    float* sPv  = hsm + 12544;            // [g*128 + tok]
    float* sNv  = hsm + 13056;
    int*   sPi  = (int*)(hsm + 13568);
    int*   sNi  = (int*)(hsm + 14080);

    int b = blockIdx.z, h = blockIdx.y, tile = blockIdx.x;
    int tid = threadIdx.x;

    for (int idx = tid; idx < 64 * 64; idx += 128) {
        int f = idx >> 6, i = idx & 63;
        srot[idx] = rot[(size_t)f * (H * 64) + h * 64 + i];
    }
    // stage q transposed: thread = token
    int t0 = tile * 128;
    {
        const float4* qr = (const float4*)(qk + ((size_t)b * S + t0 + tid) * D);
#pragma unroll
        for (int i = 0; i < 16; i++) {
            float4 f4 = qr[i];
            sqT[(4*i + 0) * HQ_STRIDE + tid] = f4.x;
            sqT[(4*i + 1) * HQ_STRIDE + tid] = f4.y;
            sqT[(4*i + 2) * HQ_STRIDE + tid] = f4.z;
            sqT[(4*i + 3) * HQ_STRIDE + tid] = f4.w;
        }
    }
    __syncthreads();

    int g = tid >> 5, lane = tid & 31;    // warp = output group g (cols g*16..g*16+15)
    ull acc[32];                           // [tok*8 + pair]
#pragma unroll
    for (int i = 0; i < 32; i++) acc[i] = 0ull;

    const float* rbase = srot + g * 16;
    const float* qbase = sqT + lane * 4;
    for (int f = 0; f < 64; f++) {
        const ulonglong2* rp = (const ulonglong2*)(rbase + f * 64);
        ulonglong2 u0 = rp[0], u1 = rp[1];
        float4 q4 = *(const float4*)(qbase + f * HQ_STRIDE);
        ull rr[4] = { u0.x, u0.y, u1.x, u1.y };
        float qa[4] = { q4.x, q4.y, q4.z, q4.w };
#pragma unroll
        for (int tt = 0; tt < 4; tt++) {
            ull qq = pack2(qa[tt], qa[tt]);
#pragma unroll
            for (int i = 0; i < 4; i++)
                acc[tt*8 + i] = fma2(qq, rr[i], acc[tt*8 + i]);
        }
        const ulonglong2* rp2 = (const ulonglong2*)(rbase + f * 64 + 8);
        ulonglong2 u2 = rp2[0], u3 = rp2[1];
        ull rr2[4] = { u2.x, u2.y, u3.x, u3.y };
#pragma unroll
        for (int tt = 0; tt < 4; tt++) {
            ull qq = pack2(qa[tt], qa[tt]);
#pragma unroll
            for (int i = 0; i < 4; i++)
                acc[tt*8 + 4 + i] = fma2(qq, rr2[i], acc[tt*8 + 4 + i]);
        }
    }

    // local argmax over this group's 16 columns, per token
#pragma unroll
    for (int tt = 0; tt < 4; tt++) {
        float bestP = -INFINITY, bestN = -INFINITY;
        int ip = 0, inn = 0;
#pragma unroll
        for (int i = 0; i < 8; i++) {
            float lo, hi; unpack2(lo, hi, acc[tt*8 + i]);
            int col = g * 16 + 2 * i;
            if (lo > bestP)  { bestP = lo;  ip  = col;     }
            if (hi > bestP)  { bestP = hi;  ip  = col + 1; }
            if (-lo > bestN) { bestN = -lo; inn = col;     }
            if (-hi > bestN) { bestN = -hi; inn = col + 1; }
        }
        int tok = lane * 4 + tt;
        sPv[g * 128 + tok] = bestP; sPi[g * 128 + tok] = ip;
        sNv[g * 128 + tok] = bestN; sNi[g * 128 + tok] = inn;
    }
    __syncthreads();

    // cross-group reduce (ascending g keeps first occurrence on ties)
    {
        float bestP = sPv[tid], bestN = sNv[tid];
        int ip = sPi[tid], inn = sNi[tid];
#pragma unroll
        for (int gg = 1; gg < 4; gg++) {
            float v = sPv[gg * 128 + tid];
            if (v > bestP) { bestP = v; ip = sPi[gg * 128 + tid]; }
            float w = sNv[gg * 128 + tid];
            if (w > bestN) { bestN = w; inn = sNi[gg * 128 + tid]; }
        }
        int bucket = (bestP >= bestN) ? ip : (64 + inn);
        g_bucket[((size_t)b * H + h) * S + t0 + tid] = (unsigned char)bucket;
    }
}

// ============================================================
// K2: stable counting sort per (b,h)
// ============================================================
__global__ __launch_bounds__(128) void sort_kernel()
{
    int bh = blockIdx.x;
    __shared__ unsigned char sb[S];
    __shared__ int hist[NB];
    __shared__ int base[NB];
    int tid = threadIdx.x;

    hist[tid] = 0;
    __syncthreads();

    const uchar4* src = (const uchar4*)(g_bucket + (size_t)bh * S);
    for (int i = tid; i < S / 4; i += 128) {
        uchar4 u = src[i];
        ((uchar4*)sb)[i] = u;
        atomicAdd(&hist[u.x], 1);
        atomicAdd(&hist[u.y], 1);
        atomicAdd(&hist[u.z], 1);
        atomicAdd(&hist[u.w], 1);
    }
    __syncthreads();

    if (tid == 0) {
        int s = 0;
        for (int k = 0; k < NB; k++) { base[k] = s; s += hist[k]; }
    }
    __syncthreads();

    int myb = tid;
    int cnt = base[myb];
    unsigned short* dst = g_st + (size_t)bh * S;
    for (int i = 0; i < S; i += 4) {
        uchar4 u = *(const uchar4*)(sb + i);
        if (u.x == myb) dst[cnt++] = (unsigned short)(i);
        if (u.y == myb) dst[cnt++] = (unsigned short)(i + 1);
        if (u.z == myb) dst[cnt++] = (unsigned short)(i + 2);
        if (u.w == myb) dst[cnt++] = (unsigned short)(i + 3);
    }
}

// ============================================================
// K3: mma.sync attention v3.
//  - MMA1: bf16, 2-pass (qh*kh + ql*kh); B reads hi plane only.
//    (dropped q*k_lo term ~1.5e-4 absolute in s — safe for exp)
//  - MMA2: fp16, 2-pass (Ph*Vh + Pl*Vh); V single fp16 plane.
//    (dropped P*V_lo ~5e-4 worst-element relative on O)
//  - smem 55KB
//
// smem bytes:
//   0      skid[128]        512 srn[128]
//   1024   KQhi 128x72bf16 (18432)  [Phi fp16 64x136 aliases]
//   19456  KQlo 128x72bf16 (18432)  [Plo fp16 64x136 aliases]
//   37888  Vh   128x72fp16 (18432)  total 56320
// ============================================================
#define SM_SKID 0
#define SM_SRN  512
#define SM_KQHI 1024
#define SM_KQLO 19456
#define SM_PHI  1024
#define SM_PLO  19456
#define SM_VH   37888
#define ATTN_SMEM_B 56320
#define KQ_STRIDE 144     // bytes (72 bf16)
#define P_STRIDE  272     // bytes (136 fp16)

__global__ __launch_bounds__(128) void attn_kernel(const float* __restrict__ qk,
                                                   const float* __restrict__ vin)
{
    extern __shared__ char smem[];
    unsigned sbase = smem_u32(smem);
    int tid = threadIdx.x;
    int b = blockIdx.y, c = blockIdx.x, h = c >> 7;
    int* skid = (int*)(smem + SM_SKID);
    float* srn_s = (float*)(smem + SM_SRN);

    // ---------------- staging: thread = key slot ----------------
    {
        int slot = tid;
        int kc = (slot < 64) ? c : ((c + CHUNKS - 1) & (CHUNKS - 1));
        const unsigned short* ST = g_st + (size_t)b * (H * S);
        int kt = ST[kc * BSZ + (slot & 63)];
        skid[slot] = kt;

        float kv[64];
        float ss = 0.f;
        const float4* kr = (const float4*)(qk + ((size_t)b * S + kt) * D);
#pragma unroll
        for (int i = 0; i < 16; i++) {
            float4 f4 = kr[i];
            kv[4*i] = f4.x; kv[4*i+1] = f4.y; kv[4*i+2] = f4.z; kv[4*i+3] = f4.w;
            ss += f4.x*f4.x + f4.y*f4.y + f4.z*f4.z + f4.w*f4.w;
        }
        srn_s[slot] = 0.125f / fmaxf(sqrtf(ss), 1e-12f);

        // raw KQ rows (bf16 hi/lo)
#pragma unroll
        for (int g = 0; g < 8; g++) {
            uint4 hi4, lo4;
            unsigned* hw = (unsigned*)&hi4;
            unsigned* lw = (unsigned*)&lo4;
#pragma unroll
            for (int e = 0; e < 4; e++) {
                __nv_bfloat16 h0, l0, h1, l1;
                bsplit(kv[g*8 + 2*e],     h0, l0);
                bsplit(kv[g*8 + 2*e + 1], h1, l1);
                hw[e] = bpair(h0, h1); lw[e] = bpair(l0, l1);
            }
            *(uint4*)(smem + SM_KQHI + slot * KQ_STRIDE + g * 16) = hi4;
            *(uint4*)(smem + SM_KQLO + slot * KQ_STRIDE + g * 16) = lo4;
        }

        // V rows: single fp16 plane, row-major
        const float4* vr = (const float4*)(vin + ((size_t)b * S + kt) * D);
#pragma unroll
        for (int i = 0; i < 8; i++) {
            float4 fa = vr[2*i], fb = vr[2*i + 1];
            uint4 h4;
            unsigned* hw = (unsigned*)&h4;
            hw[0] = hpair(__float2half_rn(fa.x), __float2half_rn(fa.y));
            hw[1] = hpair(__float2half_rn(fa.z), __float2half_rn(fa.w));
            hw[2] = hpair(__float2half_rn(fb.x), __float2half_rn(fb.y));
            hw[3] = hpair(__float2half_rn(fb.z), __float2half_rn(fb.w));
            *(uint4*)(smem + SM_VH + slot * KQ_STRIDE + i * 16) = h4;
        }
    }
    __syncthreads();

    int lane = tid & 31, warp = tid >> 5;
    int wr = warp * 16;
    int g = lane >> 2, tg = lane & 3;

    unsigned aRowOff = (unsigned)((wr + (lane & 15)) * KQ_STRIDE + (lane >> 4) * 16);
    unsigned bn  = (lane & 7) + ((lane >> 4) << 3);
    unsigned bkh = (lane >> 3) & 1;

    // ---------------- MMA1: 2-pass bf16 ----------------
    float cS[64];
#pragma unroll
    for (int i = 0; i < 64; i++) cS[i] = 0.f;

#pragma unroll
    for (int ks = 0; ks < 4; ks++) {
        unsigned aaddr = sbase + SM_KQHI + aRowOff + ks * 32;
        unsigned aH0, aH1, aH2, aH3, aL0, aL1, aL2, aL3;
        ldsm4(aH0, aH1, aH2, aH3, aaddr);
        ldsm4(aL0, aL1, aL2, aL3, aaddr + (SM_KQLO - SM_KQHI));
#pragma unroll
        for (int jp = 0; jp < 8; jp++) {
            unsigned baddr = sbase + SM_KQHI + (jp * 16 + bn) * KQ_STRIDE + bkh * 16 + ks * 32;
            unsigned bH0, bH1, bH2, bH3;
            ldsm4(bH0, bH1, bH2, bH3, baddr);
            float* c0 = cS + (2*jp) * 4;
            float* c1 = cS + (2*jp + 1) * 4;
            mma_bf(c0, aH0, aH1, aH2, aH3, bH0, bH1);
            mma_bf(c0, aL0, aL1, aL2, aL3, bH0, bH1);
            mma_bf(c1, aH0, aH1, aH2, aH3, bH2, bH3);
            mma_bf(c1, aL0, aL1, aL2, aL3, bH2, bH3);
        }
    }

    // ---------------- epilogue: scale + mask + exp + fp16 P split ----------------
    int r1 = wr + g, r2 = r1 + 8;
    int tok1 = skid[r1], tok2 = skid[r2];
    float l1 = 0.f, l2 = 0.f;

    __syncthreads();   // all warps done reading KQ before P overwrites it

#pragma unroll
    for (int j = 0; j < 16; j++) {
        int jc = j * 8 + tg * 2;
        int kid0 = skid[jc], kid1 = skid[jc + 1];
        float sc0 = srn_s[jc], sc1 = srn_s[jc + 1];
        float p00 = (kid0 == tok1) ? 0.f : __expf(cS[j*4 + 0] * sc0);
        float p01 = (kid1 == tok1) ? 0.f : __expf(cS[j*4 + 1] * sc1);
        float p10 = (kid0 == tok2) ? 0.f : __expf(cS[j*4 + 2] * sc0);
        float p11 = (kid1 == tok2) ? 0.f : __expf(cS[j*4 + 3] * sc1);
        l1 += p00 + p01;
        l2 += p10 + p11;
        __half ha = __float2half_rn(p00), hb = __float2half_rn(p01);
        __half la = __float2half_rn(p00 - __half2float(ha));
        __half lb = __float2half_rn(p01 - __half2float(hb));
        *(unsigned*)(smem + SM_PHI + r1 * P_STRIDE + jc * 2) = hpair(ha, hb);
        *(unsigned*)(smem + SM_PLO + r1 * P_STRIDE + jc * 2) = hpair(la, lb);
        ha = __float2half_rn(p10); hb = __float2half_rn(p11);
        la = __float2half_rn(p10 - __half2float(ha));
        lb = __float2half_rn(p11 - __half2float(hb));
        *(unsigned*)(smem + SM_PHI + r2 * P_STRIDE + jc * 2) = hpair(ha, hb);
        *(unsigned*)(smem + SM_PLO + r2 * P_STRIDE + jc * 2) = hpair(la, lb);
    }

    l1 += __shfl_xor_sync(0xffffffffu, l1, 1);
    l1 += __shfl_xor_sync(0xffffffffu, l1, 2);
    l2 += __shfl_xor_sync(0xffffffffu, l2, 1);
    l2 += __shfl_xor_sync(0xffffffffu, l2, 2);
    float linv1 = 1.f / l1, linv2 = 1.f / l2;
    if (tg == 0) {
        size_t lbase = (size_t)(b * H + h) * S;
        g_logits[lbase + tok1] = __logf(l1);
        g_logits[lbase + tok2] = __logf(l2);
    }
    __syncwarp();      // P stores visible to own-warp ldmatrix (A reads own rows only)

    // ---------------- MMA2: 2-pass fp16 (V hi plane only) ----------------
    float oacc[32];
#pragma unroll
    for (int i = 0; i < 32; i++) oacc[i] = 0.f;

    unsigned a2RowOff = (unsigned)((wr + (lane & 15)) * P_STRIDE + (lane >> 4) * 16);
    unsigned vRow = lane & 15, vColHalf = lane >> 4;
#pragma unroll
    for (int ks = 0; ks < 8; ks++) {
        unsigned aaddr = sbase + SM_PHI + a2RowOff + ks * 32;
        unsigned pH0, pH1, pH2, pH3, pL0, pL1, pL2, pL3;
        ldsm4(pH0, pH1, pH2, pH3, aaddr);
        ldsm4(pL0, pL1, pL2, pL3, aaddr + (SM_PLO - SM_PHI));
#pragma unroll
        for (int jp = 0; jp < 4; jp++) {
            unsigned baddr = sbase + SM_VH + (ks * 16 + vRow) * KQ_STRIDE + vColHalf * 16 + jp * 32;
            unsigned vH0, vH1, vH2, vH3;
            ldsm4t(vH0, vH1, vH2, vH3, baddr);
            float* o0 = oacc + (2*jp) * 4;
            float* o1 = oacc + (2*jp + 1) * 4;
            mma_fp16(o0, pH0, pH1, pH2, pH3, vH0, vH1);
            mma_fp16(o0, pL0, pL1, pL2, pL3, vH0, vH1);
            mma_fp16(o1, pH0, pH1, pH2, pH3, vH2, vH3);
            mma_fp16(o1, pL0, pL1, pL2, pL3, vH2, vH3);
        }
    }

    // ---------------- normalize + scatter (the unsort) ----------------
    float* orow1 = g_o + (((size_t)(b * H + h) * S + tok1) * D);
    float* orow2 = g_o + (((size_t)(b * H + h) * S + tok2) * D);
#pragma unroll
    for (int j = 0; j < 8; j++) {
        int col = j * 8 + tg * 2;
        float2 w1 = make_float2(oacc[j*4 + 0] * linv1, oacc[j*4 + 1] * linv1);
        float2 w2 = make_float2(oacc[j*4 + 2] * linv2, oacc[j*4 + 3] * linv2);
        *(float2*)(orow1 + col) = w1;
        *(float2*)(orow2 + col) = w2;
    }
}

// ============================================================
// K4: combine the H rounds with softmax(logits) weights.
// ============================================================
__global__ __launch_bounds__(256) void combine_kernel(float* __restrict__ out)
{
    int bt = blockIdx.x * 4 + (threadIdx.x >> 6);
    int b = bt >> 13, t = bt & (S - 1);
    int d = threadIdx.x & 63;

    float lg[H];
    float mx = -INFINITY;
#pragma unroll
    for (int h = 0; h < H; h++) {
        lg[h] = g_logits[((size_t)(b * H + h)) * S + t];
        mx = fmaxf(mx, lg[h]);
    }
    float sum = 0.f;
#pragma unroll
    for (int h = 0; h < H; h++) { lg[h] = __expf(lg[h] - mx); sum += lg[h]; }

    float a = 0.f;
#pragma unroll
    for (int h = 0; h < H; h++)
        a += lg[h] * g_o[(((size_t)(b * H + h)) * S + t) * D + d];

    out[((size_t)b * S + t) * D + d] = a / sum;
}

// ============================================================
extern "C" void kernel_launch(void* const* d_in, const int* in_sizes, int n_in,
                              void* d_out, int out_size)
{
    const float* qk  = (const float*)d_in[0];
    const float* v   = (const float*)d_in[1];
    const float* rot = (const float*)d_in[2];
    float* out = (float*)d_out;

    cudaFuncSetAttribute(attn_kernel, cudaFuncAttributeMaxDynamicSharedMemorySize, ATTN_SMEM_B);
    cudaFuncSetAttribute(hash_kernel, cudaFuncAttributeMaxDynamicSharedMemorySize, HASH_SMEM_B);

    hash_kernel<<<dim3(S / 128, H, B), 128, HASH_SMEM_B>>>(qk, rot);
    sort_kernel<<<B * H, 128>>>();
    attn_kernel<<<dim3(CHUNKS, B), 128, ATTN_SMEM_B>>>(qk, v);
    combine_kernel<<<B * S / 4, 256>>>(out);
}

// round 10
// speedup vs baseline: 2.6146x; 1.0315x over previous
#include <cuda_runtime.h>
#include <cuda_bf16.h>
#include <cuda_fp16.h>
#include <math.h>

#define B 8
#define S 8192
#define D 64
#define H 8
#define NB 128
#define BSZ 64
#define CHUNKS 1024

typedef unsigned long long ull;

// ---------- packed f32x2 helpers (sm_100+) ----------
__device__ __forceinline__ ull fma2(ull a, ull b, ull c) {
    ull d; asm("fma.rn.f32x2 %0, %1, %2, %3;" : "=l"(d) : "l"(a), "l"(b), "l"(c)); return d;
}
__device__ __forceinline__ ull pack2(float x, float y) {
    ull r; asm("mov.b64 %0, {%1,%2};" : "=l"(r) : "f"(x), "f"(y)); return r;
}
__device__ __forceinline__ void unpack2(float& x, float& y, ull r) {
    asm("mov.b64 {%0,%1}, %2;" : "=f"(x), "=f"(y) : "l"(r));
}

__device__ __forceinline__ unsigned smem_u32(const void* p) {
    unsigned a; asm("{ .reg .u64 t; cvta.to.shared.u64 t, %1; cvt.u32.u64 %0, t; }" : "=r"(a) : "l"(p));
    return a;
}

// ---------- warp MMA helpers (sm_80+ baseline) ----------
__device__ __forceinline__ void ldsm4(unsigned& r0, unsigned& r1, unsigned& r2, unsigned& r3,
                                      unsigned addr) {
    asm volatile("ldmatrix.sync.aligned.m8n8.x4.shared.b16 {%0,%1,%2,%3}, [%4];"
                 : "=r"(r0), "=r"(r1), "=r"(r2), "=r"(r3) : "r"(addr));
}
__device__ __forceinline__ void ldsm4t(unsigned& r0, unsigned& r1, unsigned& r2, unsigned& r3,
                                       unsigned addr) {
    asm volatile("ldmatrix.sync.aligned.m8n8.x4.trans.shared.b16 {%0,%1,%2,%3}, [%4];"
                 : "=r"(r0), "=r"(r1), "=r"(r2), "=r"(r3) : "r"(addr));
}
__device__ __forceinline__ void mma_fp16(float* c, unsigned a0, unsigned a1, unsigned a2, unsigned a3,
                                         unsigned b0, unsigned b1) {
    asm volatile("mma.sync.aligned.m16n8k16.row.col.f32.f16.f16.f32 "
                 "{%0,%1,%2,%3}, {%4,%5,%6,%7}, {%8,%9}, {%0,%1,%2,%3};"
                 : "+f"(c[0]), "+f"(c[1]), "+f"(c[2]), "+f"(c[3])
                 : "r"(a0), "r"(a1), "r"(a2), "r"(a3), "r"(b0), "r"(b1));
}
__device__ __forceinline__ unsigned hpair(__half a, __half b) {
    __half2 p; p.x = a; p.y = b;
    return *(unsigned*)&p;
}

// -------- device scratch --------
__device__ unsigned char  g_bucket[B * H * S];
__device__ unsigned short g_st[B * H * S];
__device__ float          g_logits[B * H * S];
__device__ __half         g_o[(size_t)B * H * S * D];   // fp16: halves O traffic

// ============================================================
// K1: LSH hashing (fp32 — argmax stability requires it).
// 128 threads, q transposed in smem, warp = 16-output group.
// ============================================================
#define HQ_STRIDE 132
#define HASH_SMEM_B 58368

__global__ __launch_bounds__(128) void hash_kernel(const float* __restrict__ qk,
                                                   const float* __restrict__ rot)
{
    extern __shared__ float hsm[];
    float* srot = hsm;                    // [f*64 + i]
    float* sqT  = hsm + 4096;             // [f*132 + tok]
    float* sPv  = hsm + 12544;            // [g*128 + tok]
    float* sNv  = hsm + 13056;
    int*   sPi  = (int*)(hsm + 13568);
    int*   sNi  = (int*)(hsm + 14080);

    int b = blockIdx.z, h = blockIdx.y, tile = blockIdx.x;
    int tid = threadIdx.x;

    for (int idx = tid; idx < 64 * 64; idx += 128) {
        int f = idx >> 6, i = idx & 63;
        srot[idx] = rot[(size_t)f * (H * 64) + h * 64 + i];
    }
    int t0 = tile * 128;
    {
        const float4* qr = (const float4*)(qk + ((size_t)b * S + t0 + tid) * D);
#pragma unroll
        for (int i = 0; i < 16; i++) {
            float4 f4 = qr[i];
            sqT[(4*i + 0) * HQ_STRIDE + tid] = f4.x;
            sqT[(4*i + 1) * HQ_STRIDE + tid] = f4.y;
            sqT[(4*i + 2) * HQ_STRIDE + tid] = f4.z;
            sqT[(4*i + 3) * HQ_STRIDE + tid] = f4.w;
        }
    }
    __syncthreads();

    int g = tid >> 5, lane = tid & 31;
    ull acc[32];
#pragma unroll
    for (int i = 0; i < 32; i++) acc[i] = 0ull;

    const float* rbase = srot + g * 16;
    const float* qbase = sqT + lane * 4;
    for (int f = 0; f < 64; f++) {
        const ulonglong2* rp = (const ulonglong2*)(rbase + f * 64);
        ulonglong2 u0 = rp[0], u1 = rp[1];
        float4 q4 = *(const float4*)(qbase + f * HQ_STRIDE);
        ull rr[4] = { u0.x, u0.y, u1.x, u1.y };
        float qa[4] = { q4.x, q4.y, q4.z, q4.w };
#pragma unroll
        for (int tt = 0; tt < 4; tt++) {
            ull qq = pack2(qa[tt], qa[tt]);
#pragma unroll
            for (int i = 0; i < 4; i++)
                acc[tt*8 + i] = fma2(qq, rr[i], acc[tt*8 + i]);
        }
        const ulonglong2* rp2 = (const ulonglong2*)(rbase + f * 64 + 8);
        ulonglong2 u2 = rp2[0], u3 = rp2[1];
        ull rr2[4] = { u2.x, u2.y, u3.x, u3.y };
#pragma unroll
        for (int tt = 0; tt < 4; tt++) {
            ull qq = pack2(qa[tt], qa[tt]);
#pragma unroll
            for (int i = 0; i < 4; i++)
                acc[tt*8 + 4 + i] = fma2(qq, rr2[i], acc[tt*8 + 4 + i]);
        }
    }

#pragma unroll
    for (int tt = 0; tt < 4; tt++) {
        float bestP = -INFINITY, bestN = -INFINITY;
        int ip = 0, inn = 0;
#pragma unroll
        for (int i = 0; i < 8; i++) {
            float lo, hi; unpack2(lo, hi, acc[tt*8 + i]);
            int col = g * 16 + 2 * i;
            if (lo > bestP)  { bestP = lo;  ip  = col;     }
            if (hi > bestP)  { bestP = hi;  ip  = col + 1; }
            if (-lo > bestN) { bestN = -lo; inn = col;     }
            if (-hi > bestN) { bestN = -hi; inn = col + 1; }
        }
        int tok = lane * 4 + tt;
        sPv[g * 128 + tok] = bestP; sPi[g * 128 + tok] = ip;
        sNv[g * 128 + tok] = bestN; sNi[g * 128 + tok] = inn;
    }
    __syncthreads();

    {
        float bestP = sPv[tid], bestN = sNv[tid];
        int ip = sPi[tid], inn = sNi[tid];
#pragma unroll
        for (int gg = 1; gg < 4; gg++) {
            float v = sPv[gg * 128 + tid];
            if (v > bestP) { bestP = v; ip = sPi[gg * 128 + tid]; }
            float w = sNv[gg * 128 + tid];
            if (w > bestN) { bestN = w; inn = sNi[gg * 128 + tid]; }
        }
        int bucket = (bestP >= bestN) ? ip : (64 + inn);
        g_bucket[((size_t)b * H + h) * S + t0 + tid] = (unsigned char)bucket;
    }
}

// ============================================================
// K2: stable counting sort per (b,h)
// ============================================================
__global__ __launch_bounds__(128) void sort_kernel()
{
    int bh = blockIdx.x;
    __shared__ unsigned char sb[S];
    __shared__ int hist[NB];
    __shared__ int base[NB];
    int tid = threadIdx.x;

    hist[tid] = 0;
    __syncthreads();

    const uchar4* src = (const uchar4*)(g_bucket + (size_t)bh * S);
    for (int i = tid; i < S / 4; i += 128) {
        uchar4 u = src[i];
        ((uchar4*)sb)[i] = u;
        atomicAdd(&hist[u.x], 1);
        atomicAdd(&hist[u.y], 1);
        atomicAdd(&hist[u.z], 1);
        atomicAdd(&hist[u.w], 1);
    }
    __syncthreads();

    if (tid == 0) {
        int s = 0;
        for (int k = 0; k < NB; k++) { base[k] = s; s += hist[k]; }
    }
    __syncthreads();

    int myb = tid;
    int cnt = base[myb];
    unsigned short* dst = g_st + (size_t)bh * S;
    for (int i = 0; i < S; i += 4) {
        uchar4 u = *(const uchar4*)(sb + i);
        if (u.x == myb) dst[cnt++] = (unsigned short)(i);
        if (u.y == myb) dst[cnt++] = (unsigned short)(i + 1);
        if (u.z == myb) dst[cnt++] = (unsigned short)(i + 2);
        if (u.w == myb) dst[cnt++] = (unsigned short)(i + 3);
    }
}

// ============================================================
// K3: mma.sync attention v4.
//  - MMA1: single-pass fp16 (err ~9e-5 in s, better than bf16 2-pass)
//  - MMA2: fp16 2-pass (P hi+lo), V single fp16 plane
//  - O written fp16
//
// smem bytes:
//   0      skid[128]        512 srn[128]
//   1024   KQ fp16 128x72 (18432)  [Phi fp16 64x136 = 17408 aliases]
//   19456  Plo fp16 64x136 (17408)
//   36864  V  fp16 128x72 (18432)  total 55296
// ============================================================
#define SM_SKID 0
#define SM_SRN  512
#define SM_KQ   1024
#define SM_PHI  1024
#define SM_PLO  19456
#define SM_VH   36864
#define ATTN_SMEM_B 55296
#define KQ_STRIDE 144     // bytes (72 fp16)
#define P_STRIDE  272     // bytes (136 fp16)

__global__ __launch_bounds__(128) void attn_kernel(const float* __restrict__ qk,
                                                   const float* __restrict__ vin)
{
    extern __shared__ char smem[];
    unsigned sbase = smem_u32(smem);
    int tid = threadIdx.x;
    int b = blockIdx.y, c = blockIdx.x, h = c >> 7;
    int* skid = (int*)(smem + SM_SKID);
    float* srn_s = (float*)(smem + SM_SRN);

    // ---------------- staging: thread = key slot ----------------
    {
        int slot = tid;
        int kc = (slot < 64) ? c : ((c + CHUNKS - 1) & (CHUNKS - 1));
        const unsigned short* ST = g_st + (size_t)b * (H * S);
        int kt = ST[kc * BSZ + (slot & 63)];
        skid[slot] = kt;

        float kv[64];
        float ss = 0.f;
        const float4* kr = (const float4*)(qk + ((size_t)b * S + kt) * D);
#pragma unroll
        for (int i = 0; i < 16; i++) {
            float4 f4 = kr[i];
            kv[4*i] = f4.x; kv[4*i+1] = f4.y; kv[4*i+2] = f4.z; kv[4*i+3] = f4.w;
            ss += f4.x*f4.x + f4.y*f4.y + f4.z*f4.z + f4.w*f4.w;
        }
        srn_s[slot] = 0.125f / fmaxf(sqrtf(ss), 1e-12f);

        // raw KQ rows, single fp16 plane
#pragma unroll
        for (int i = 0; i < 8; i++) {
            uint4 h4;
            unsigned* hw = (unsigned*)&h4;
            hw[0] = hpair(__float2half_rn(kv[8*i + 0]), __float2half_rn(kv[8*i + 1]));
            hw[1] = hpair(__float2half_rn(kv[8*i + 2]), __float2half_rn(kv[8*i + 3]));
            hw[2] = hpair(__float2half_rn(kv[8*i + 4]), __float2half_rn(kv[8*i + 5]));
            hw[3] = hpair(__float2half_rn(kv[8*i + 6]), __float2half_rn(kv[8*i + 7]));
            *(uint4*)(smem + SM_KQ + slot * KQ_STRIDE + i * 16) = h4;
        }

        // V rows: single fp16 plane, row-major
        const float4* vr = (const float4*)(vin + ((size_t)b * S + kt) * D);
#pragma unroll
        for (int i = 0; i < 8; i++) {
            float4 fa = vr[2*i], fb = vr[2*i + 1];
            uint4 h4;
            unsigned* hw = (unsigned*)&h4;
            hw[0] = hpair(__float2half_rn(fa.x), __float2half_rn(fa.y));
            hw[1] = hpair(__float2half_rn(fa.z), __float2half_rn(fa.w));
            hw[2] = hpair(__float2half_rn(fb.x), __float2half_rn(fb.y));
            hw[3] = hpair(__float2half_rn(fb.z), __float2half_rn(fb.w));
            *(uint4*)(smem + SM_VH + slot * KQ_STRIDE + i * 16) = h4;
        }
    }
    __syncthreads();

    int lane = tid & 31, warp = tid >> 5;
    int wr = warp * 16;
    int g = lane >> 2, tg = lane & 3;

    unsigned aRowOff = (unsigned)((wr + (lane & 15)) * KQ_STRIDE + (lane >> 4) * 16);
    unsigned bn  = (lane & 7) + ((lane >> 4) << 3);
    unsigned bkh = (lane >> 3) & 1;

    // ---------------- MMA1: single-pass fp16 ----------------
    float cS[64];
#pragma unroll
    for (int i = 0; i < 64; i++) cS[i] = 0.f;

#pragma unroll
    for (int ks = 0; ks < 4; ks++) {
        unsigned aaddr = sbase + SM_KQ + aRowOff + ks * 32;
        unsigned aH0, aH1, aH2, aH3;
        ldsm4(aH0, aH1, aH2, aH3, aaddr);
#pragma unroll
        for (int jp = 0; jp < 8; jp++) {
            unsigned baddr = sbase + SM_KQ + (jp * 16 + bn) * KQ_STRIDE + bkh * 16 + ks * 32;
            unsigned bH0, bH1, bH2, bH3;
            ldsm4(bH0, bH1, bH2, bH3, baddr);
            mma_fp16(cS + (2*jp) * 4,     aH0, aH1, aH2, aH3, bH0, bH1);
            mma_fp16(cS + (2*jp + 1) * 4, aH0, aH1, aH2, aH3, bH2, bH3);
        }
    }

    // ---------------- epilogue: scale + mask + exp + fp16 P split ----------------
    int r1 = wr + g, r2 = r1 + 8;
    int tok1 = skid[r1], tok2 = skid[r2];
    float l1 = 0.f, l2 = 0.f;

    __syncthreads();   // all warps done reading KQ before P overwrites it

#pragma unroll
    for (int j = 0; j < 16; j++) {
        int jc = j * 8 + tg * 2;
        int kid0 = skid[jc], kid1 = skid[jc + 1];
        float sc0 = srn_s[jc], sc1 = srn_s[jc + 1];
        float p00 = (kid0 == tok1) ? 0.f : __expf(cS[j*4 + 0] * sc0);
        float p01 = (kid1 == tok1) ? 0.f : __expf(cS[j*4 + 1] * sc1);
        float p10 = (kid0 == tok2) ? 0.f : __expf(cS[j*4 + 2] * sc0);
        float p11 = (kid1 == tok2) ? 0.f : __expf(cS[j*4 + 3] * sc1);
        l1 += p00 + p01;
        l2 += p10 + p11;
        __half ha = __float2half_rn(p00), hb = __float2half_rn(p01);
        __half la = __float2half_rn(p00 - __half2float(ha));
        __half lb = __float2half_rn(p01 - __half2float(hb));
        *(unsigned*)(smem + SM_PHI + r1 * P_STRIDE + jc * 2) = hpair(ha, hb);
        *(unsigned*)(smem + SM_PLO + r1 * P_STRIDE + jc * 2) = hpair(la, lb);
        ha = __float2half_rn(p10); hb = __float2half_rn(p11);
        la = __float2half_rn(p10 - __half2float(ha));
        lb = __float2half_rn(p11 - __half2float(hb));
        *(unsigned*)(smem + SM_PHI + r2 * P_STRIDE + jc * 2) = hpair(ha, hb);
        *(unsigned*)(smem + SM_PLO + r2 * P_STRIDE + jc * 2) = hpair(la, lb);
    }

    l1 += __shfl_xor_sync(0xffffffffu, l1, 1);
    l1 += __shfl_xor_sync(0xffffffffu, l1, 2);
    l2 += __shfl_xor_sync(0xffffffffu, l2, 1);
    l2 += __shfl_xor_sync(0xffffffffu, l2, 2);
    float linv1 = 1.f / l1, linv2 = 1.f / l2;
    if (tg == 0) {
        size_t lbase = (size_t)(b * H + h) * S;
        g_logits[lbase + tok1] = __logf(l1);
        g_logits[lbase + tok2] = __logf(l2);
    }
    __syncwarp();      // P stores visible to own-warp ldmatrix (A reads own rows only)

    // ---------------- MMA2: 2-pass fp16 (V single plane) ----------------
    float oacc[32];
#pragma unroll
    for (int i = 0; i < 32; i++) oacc[i] = 0.f;

    unsigned a2RowOff = (unsigned)((wr + (lane & 15)) * P_STRIDE + (lane >> 4) * 16);
    unsigned vRow = lane & 15, vColHalf = lane >> 4;
#pragma unroll
    for (int ks = 0; ks < 8; ks++) {
        unsigned aaddr = sbase + SM_PHI + a2RowOff + ks * 32;
        unsigned pH0, pH1, pH2, pH3, pL0, pL1, pL2, pL3;
        ldsm4(pH0, pH1, pH2, pH3, aaddr);
        ldsm4(pL0, pL1, pL2, pL3, aaddr + (SM_PLO - SM_PHI));
#pragma unroll
        for (int jp = 0; jp < 4; jp++) {
            unsigned baddr = sbase + SM_VH + (ks * 16 + vRow) * KQ_STRIDE + vColHalf * 16 + jp * 32;
            unsigned vH0, vH1, vH2, vH3;
            ldsm4t(vH0, vH1, vH2, vH3, baddr);
            float* o0 = oacc + (2*jp) * 4;
            float* o1 = oacc + (2*jp + 1) * 4;
            mma_fp16(o0, pH0, pH1, pH2, pH3, vH0, vH1);
            mma_fp16(o0, pL0, pL1, pL2, pL3, vH0, vH1);
            mma_fp16(o1, pH0, pH1, pH2, pH3, vH2, vH3);
            mma_fp16(o1, pL0, pL1, pL2, pL3, vH2, vH3);
        }
    }

    // ---------------- normalize + scatter fp16 (the unsort) ----------------
    __half* orow1 = g_o + (((size_t)(b * H + h) * S + tok1) * D);
    __half* orow2 = g_o + (((size_t)(b * H + h) * S + tok2) * D);
#pragma unroll
    for (int j = 0; j < 8; j++) {
        int col = j * 8 + tg * 2;
        *(unsigned*)(orow1 + col) = hpair(__float2half_rn(oacc[j*4 + 0] * linv1),
                                          __float2half_rn(oacc[j*4 + 1] * linv1));
        *(unsigned*)(orow2 + col) = hpair(__float2half_rn(oacc[j*4 + 2] * linv2),
                                          __float2half_rn(oacc[j*4 + 3] * linv2));
    }
}

// ============================================================
// K4: combine the H rounds with softmax(logits) weights.
// ============================================================
__global__ __launch_bounds__(256) void combine_kernel(float* __restrict__ out)
{
    int bt = blockIdx.x * 4 + (threadIdx.x >> 6);
    int b = bt >> 13, t = bt & (S - 1);
    int d = threadIdx.x & 63;

    float lg[H];
    float mx = -INFINITY;
#pragma unroll
    for (int h = 0; h < H; h++) {
        lg[h] = g_logits[((size_t)(b * H + h)) * S + t];
        mx = fmaxf(mx, lg[h]);
    }
    float sum = 0.f;
#pragma unroll
    for (int h = 0; h < H; h++) { lg[h] = __expf(lg[h] - mx); sum += lg[h]; }

    float a = 0.f;
#pragma unroll
    for (int h = 0; h < H; h++)
        a += lg[h] * __half2float(g_o[(((size_t)(b * H + h)) * S + t) * D + d]);

    out[((size_t)b * S + t) * D + d] = a / sum;
}

// ============================================================
extern "C" void kernel_launch(void* const* d_in, const int* in_sizes, int n_in,
                              void* d_out, int out_size)
{
    const float* qk  = (const float*)d_in[0];
    const float* v   = (const float*)d_in[1];
    const float* rot = (const float*)d_in[2];
    float* out = (float*)d_out;

    cudaFuncSetAttribute(attn_kernel, cudaFuncAttributeMaxDynamicSharedMemorySize, ATTN_SMEM_B);
    cudaFuncSetAttribute(hash_kernel, cudaFuncAttributeMaxDynamicSharedMemorySize, HASH_SMEM_B);

    hash_kernel<<<dim3(S / 128, H, B), 128, HASH_SMEM_B>>>(qk, rot);
    sort_kernel<<<B * H, 128>>>();
    attn_kernel<<<dim3(CHUNKS, B), 128, ATTN_SMEM_B>>>(qk, v);
    combine_kernel<<<B * S / 4, 256>>>(out);
}

// round 11
// speedup vs baseline: 2.9080x; 1.1122x over previous
#include <cuda_runtime.h>
#include <cuda_bf16.h>
#include <cuda_fp16.h>
#include <math.h>

#define B 8
#define S 8192
#define D 64
#define H 8
#define NB 128
#define BSZ 64
#define CHUNKS 1024

typedef unsigned long long ull;

// ---------- packed f32x2 helpers (sm_100+) ----------
__device__ __forceinline__ ull fma2(ull a, ull b, ull c) {
    ull d; asm("fma.rn.f32x2 %0, %1, %2, %3;" : "=l"(d) : "l"(a), "l"(b), "l"(c)); return d;
}
__device__ __forceinline__ ull pack2(float x, float y) {
    ull r; asm("mov.b64 %0, {%1,%2};" : "=l"(r) : "f"(x), "f"(y)); return r;
}
__device__ __forceinline__ void unpack2(float& x, float& y, ull r) {
    asm("mov.b64 {%0,%1}, %2;" : "=f"(x), "=f"(y) : "l"(r));
}

__device__ __forceinline__ unsigned smem_u32(const void* p) {
    unsigned a; asm("{ .reg .u64 t; cvta.to.shared.u64 t, %1; cvt.u32.u64 %0, t; }" : "=r"(a) : "l"(p));
    return a;
}

// ---------- warp MMA helpers (sm_80+ baseline) ----------
__device__ __forceinline__ void ldsm4(unsigned& r0, unsigned& r1, unsigned& r2, unsigned& r3,
                                      unsigned addr) {
    asm volatile("ldmatrix.sync.aligned.m8n8.x4.shared.b16 {%0,%1,%2,%3}, [%4];"
                 : "=r"(r0), "=r"(r1), "=r"(r2), "=r"(r3) : "r"(addr));
}
__device__ __forceinline__ void ldsm4t(unsigned& r0, unsigned& r1, unsigned& r2, unsigned& r3,
                                       unsigned addr) {
    asm volatile("ldmatrix.sync.aligned.m8n8.x4.trans.shared.b16 {%0,%1,%2,%3}, [%4];"
                 : "=r"(r0), "=r"(r1), "=r"(r2), "=r"(r3) : "r"(addr));
}
__device__ __forceinline__ void mma_fp16(float* c, unsigned a0, unsigned a1, unsigned a2, unsigned a3,
                                         unsigned b0, unsigned b1) {
    asm volatile("mma.sync.aligned.m16n8k16.row.col.f32.f16.f16.f32 "
                 "{%0,%1,%2,%3}, {%4,%5,%6,%7}, {%8,%9}, {%0,%1,%2,%3};"
                 : "+f"(c[0]), "+f"(c[1]), "+f"(c[2]), "+f"(c[3])
                 : "r"(a0), "r"(a1), "r"(a2), "r"(a3), "r"(b0), "r"(b1));
}
__device__ __forceinline__ unsigned hpair(__half a, __half b) {
    __half2 p; p.x = a; p.y = b;
    return *(unsigned*)&p;
}

// -------- device scratch --------
__device__ unsigned char  g_bucket[B * H * S];
__device__ unsigned short g_st[B * H * S];
__device__ float          g_logits[B * H * S];
__device__ __half         g_o[(size_t)B * H * S * D];   // fp16: halves O traffic

// ============================================================
// K1: LSH hashing (fp32 — argmax stability requires it).
// ============================================================
#define HQ_STRIDE 132
#define HASH_SMEM_B 58368

__global__ __launch_bounds__(128) void hash_kernel(const float* __restrict__ qk,
                                                   const float* __restrict__ rot)
{
    extern __shared__ float hsm[];
    float* srot = hsm;                    // [f*64 + i]
    float* sqT  = hsm + 4096;             // [f*132 + tok]
    float* sPv  = hsm + 12544;            // [g*128 + tok]
    float* sNv  = hsm + 13056;
    int*   sPi  = (int*)(hsm + 13568);
    int*   sNi  = (int*)(hsm + 14080);

    int b = blockIdx.z, h = blockIdx.y, tile = blockIdx.x;
    int tid = threadIdx.x;

    for (int idx = tid; idx < 64 * 64; idx += 128) {
        int f = idx >> 6, i = idx & 63;
        srot[idx] = rot[(size_t)f * (H * 64) + h * 64 + i];
    }
    int t0 = tile * 128;
    {
        const float4* qr = (const float4*)(qk + ((size_t)b * S + t0 + tid) * D);
#pragma unroll
        for (int i = 0; i < 16; i++) {
            float4 f4 = qr[i];
            sqT[(4*i + 0) * HQ_STRIDE + tid] = f4.x;
            sqT[(4*i + 1) * HQ_STRIDE + tid] = f4.y;
            sqT[(4*i + 2) * HQ_STRIDE + tid] = f4.z;
            sqT[(4*i + 3) * HQ_STRIDE + tid] = f4.w;
        }
    }
    __syncthreads();

    int g = tid >> 5, lane = tid & 31;
    ull acc[32];
#pragma unroll
    for (int i = 0; i < 32; i++) acc[i] = 0ull;

    const float* rbase = srot + g * 16;
    const float* qbase = sqT + lane * 4;
    for (int f = 0; f < 64; f++) {
        const ulonglong2* rp = (const ulonglong2*)(rbase + f * 64);
        ulonglong2 u0 = rp[0], u1 = rp[1];
        float4 q4 = *(const float4*)(qbase + f * HQ_STRIDE);
        ull rr[4] = { u0.x, u0.y, u1.x, u1.y };
        float qa[4] = { q4.x, q4.y, q4.z, q4.w };
#pragma unroll
        for (int tt = 0; tt < 4; tt++) {
            ull qq = pack2(qa[tt], qa[tt]);
#pragma unroll
            for (int i = 0; i < 4; i++)
                acc[tt*8 + i] = fma2(qq, rr[i], acc[tt*8 + i]);
        }
        const ulonglong2* rp2 = (const ulonglong2*)(rbase + f * 64 + 8);
        ulonglong2 u2 = rp2[0], u3 = rp2[1];
        ull rr2[4] = { u2.x, u2.y, u3.x, u3.y };
#pragma unroll
        for (int tt = 0; tt < 4; tt++) {
            ull qq = pack2(qa[tt], qa[tt]);
#pragma unroll
            for (int i = 0; i < 4; i++)
                acc[tt*8 + 4 + i] = fma2(qq, rr2[i], acc[tt*8 + 4 + i]);
        }
    }

#pragma unroll
    for (int tt = 0; tt < 4; tt++) {
        float bestP = -INFINITY, bestN = -INFINITY;
        int ip = 0, inn = 0;
#pragma unroll
        for (int i = 0; i < 8; i++) {
            float lo, hi; unpack2(lo, hi, acc[tt*8 + i]);
            int col = g * 16 + 2 * i;
            if (lo > bestP)  { bestP = lo;  ip  = col;     }
            if (hi > bestP)  { bestP = hi;  ip  = col + 1; }
            if (-lo > bestN) { bestN = -lo; inn = col;     }
            if (-hi > bestN) { bestN = -hi; inn = col + 1; }
        }
        int tok = lane * 4 + tt;
        sPv[g * 128 + tok] = bestP; sPi[g * 128 + tok] = ip;
        sNv[g * 128 + tok] = bestN; sNi[g * 128 + tok] = inn;
    }
    __syncthreads();

    {
        float bestP = sPv[tid], bestN = sNv[tid];
        int ip = sPi[tid], inn = sNi[tid];
#pragma unroll
        for (int gg = 1; gg < 4; gg++) {
            float v = sPv[gg * 128 + tid];
            if (v > bestP) { bestP = v; ip = sPi[gg * 128 + tid]; }
            float w = sNv[gg * 128 + tid];
            if (w > bestN) { bestN = w; inn = sNi[gg * 128 + tid]; }
        }
        int bucket = (bestP >= bestN) ? ip : (64 + inn);
        g_bucket[((size_t)b * H + h) * S + t0 + tid] = (unsigned char)bucket;
    }
}

// ============================================================
// K2: stable counting sort per (b,h)
// ============================================================
__global__ __launch_bounds__(128) void sort_kernel()
{
    int bh = blockIdx.x;
    __shared__ unsigned char sb[S];
    __shared__ int hist[NB];
    __shared__ int base[NB];
    int tid = threadIdx.x;

    hist[tid] = 0;
    __syncthreads();

    const uchar4* src = (const uchar4*)(g_bucket + (size_t)bh * S);
    for (int i = tid; i < S / 4; i += 128) {
        uchar4 u = src[i];
        ((uchar4*)sb)[i] = u;
        atomicAdd(&hist[u.x], 1);
        atomicAdd(&hist[u.y], 1);
        atomicAdd(&hist[u.z], 1);
        atomicAdd(&hist[u.w], 1);
    }
    __syncthreads();

    if (tid == 0) {
        int s = 0;
        for (int k = 0; k < NB; k++) { base[k] = s; s += hist[k]; }
    }
    __syncthreads();

    int myb = tid;
    int cnt = base[myb];
    unsigned short* dst = g_st + (size_t)bh * S;
    for (int i = 0; i < S; i += 4) {
        uchar4 u = *(const uchar4*)(sb + i);
        if (u.x == myb) dst[cnt++] = (unsigned short)(i);
        if (u.y == myb) dst[cnt++] = (unsigned short)(i + 1);
        if (u.z == myb) dst[cnt++] = (unsigned short)(i + 2);
        if (u.w == myb) dst[cnt++] = (unsigned short)(i + 3);
    }
}

// ============================================================
// K3: mma.sync attention v5.
//  - cooperative COALESCED gather: warp loads 2 rows/instr
//    (16 lanes x 16B per row) -> 8x fewer L1tex wavefronts
//  - MMA1 single-pass fp16; MMA2 fp16 2-pass; O fp16
//
// smem bytes:
//   0      skid[128]        512 srn[128]
//   1024   KQ fp16 128x72 (18432)  [Phi fp16 64x136 = 17408 aliases]
//   19456  Plo fp16 64x136 (17408)
//   36864  V  fp16 128x72 (18432)  total 55296
// ============================================================
#define SM_SKID 0
#define SM_SRN  512
#define SM_KQ   1024
#define SM_PHI  1024
#define SM_PLO  19456
#define SM_VH   36864
#define ATTN_SMEM_B 55296
#define KQ_STRIDE 144     // bytes (72 fp16)
#define P_STRIDE  272     // bytes (136 fp16)

__global__ __launch_bounds__(128) void attn_kernel(const float* __restrict__ qk,
                                                   const float* __restrict__ vin)
{
    extern __shared__ char smem[];
    unsigned sbase = smem_u32(smem);
    int tid = threadIdx.x;
    int b = blockIdx.y, c = blockIdx.x, h = c >> 7;
    int* skid = (int*)(smem + SM_SKID);
    float* srn_s = (float*)(smem + SM_SRN);

    int lane = tid & 31, warp = tid >> 5;

    // ---------------- staging: cooperative coalesced gather ----------------
    {
        int slot = tid;
        int kc = (slot < 64) ? c : ((c + CHUNKS - 1) & (CHUNKS - 1));
        const unsigned short* ST = g_st + (size_t)b * (H * S);
        int kt = ST[kc * BSZ + (slot & 63)];
        skid[slot] = kt;

        int wbase = warp * 32;
        int sub = lane >> 4;        // which of the 2 rows this lane serves
        int q4i = lane & 15;        // float4 index within the row
        const size_t brow = (size_t)b * S;

#pragma unroll
        for (int it = 0; it < 16; it++) {
            int s2 = wbase + it * 2 + sub;
            int tok = __shfl_sync(0xffffffffu, kt, it * 2 + sub);

            // K row: coalesced 16B/lane
            float4 f4 = ((const float4*)(qk + (brow + tok) * D))[q4i];
            float ss = f4.x*f4.x + f4.y*f4.y + f4.z*f4.z + f4.w*f4.w;
            ss += __shfl_xor_sync(0xffffffffu, ss, 1);
            ss += __shfl_xor_sync(0xffffffffu, ss, 2);
            ss += __shfl_xor_sync(0xffffffffu, ss, 4);
            ss += __shfl_xor_sync(0xffffffffu, ss, 8);
            if (q4i == 0)
                srn_s[s2] = 0.125f / fmaxf(sqrtf(ss), 1e-12f);
            uint2 kp;
            kp.x = hpair(__float2half_rn(f4.x), __float2half_rn(f4.y));
            kp.y = hpair(__float2half_rn(f4.z), __float2half_rn(f4.w));
            *(uint2*)(smem + SM_KQ + s2 * KQ_STRIDE + q4i * 8) = kp;

            // V row: coalesced 16B/lane
            float4 v4 = ((const float4*)(vin + (brow + tok) * D))[q4i];
            uint2 vp;
            vp.x = hpair(__float2half_rn(v4.x), __float2half_rn(v4.y));
            vp.y = hpair(__float2half_rn(v4.z), __float2half_rn(v4.w));
            *(uint2*)(smem + SM_VH + s2 * KQ_STRIDE + q4i * 8) = vp;
        }
    }
    __syncthreads();

    int wr = warp * 16;
    int g = lane >> 2, tg = lane & 3;

    unsigned aRowOff = (unsigned)((wr + (lane & 15)) * KQ_STRIDE + (lane >> 4) * 16);
    unsigned bn  = (lane & 7) + ((lane >> 4) << 3);
    unsigned bkh = (lane >> 3) & 1;

    // ---------------- MMA1: single-pass fp16 ----------------
    float cS[64];
#pragma unroll
    for (int i = 0; i < 64; i++) cS[i] = 0.f;

#pragma unroll
    for (int ks = 0; ks < 4; ks++) {
        unsigned aaddr = sbase + SM_KQ + aRowOff + ks * 32;
        unsigned aH0, aH1, aH2, aH3;
        ldsm4(aH0, aH1, aH2, aH3, aaddr);
#pragma unroll
        for (int jp = 0; jp < 8; jp++) {
            unsigned baddr = sbase + SM_KQ + (jp * 16 + bn) * KQ_STRIDE + bkh * 16 + ks * 32;
            unsigned bH0, bH1, bH2, bH3;
            ldsm4(bH0, bH1, bH2, bH3, baddr);
            mma_fp16(cS + (2*jp) * 4,     aH0, aH1, aH2, aH3, bH0, bH1);
            mma_fp16(cS + (2*jp + 1) * 4, aH0, aH1, aH2, aH3, bH2, bH3);
        }
    }

    // ---------------- epilogue: scale + mask + exp + fp16 P split ----------------
    int r1 = wr + g, r2 = r1 + 8;
    int tok1 = skid[r1], tok2 = skid[r2];
    float l1 = 0.f, l2 = 0.f;

    __syncthreads();   // all warps done reading KQ before P overwrites it

#pragma unroll
    for (int j = 0; j < 16; j++) {
        int jc = j * 8 + tg * 2;
        int kid0 = skid[jc], kid1 = skid[jc + 1];
        float sc0 = srn_s[jc], sc1 = srn_s[jc + 1];
        float p00 = (kid0 == tok1) ? 0.f : __expf(cS[j*4 + 0] * sc0);
        float p01 = (kid1 == tok1) ? 0.f : __expf(cS[j*4 + 1] * sc1);
        float p10 = (kid0 == tok2) ? 0.f : __expf(cS[j*4 + 2] * sc0);
        float p11 = (kid1 == tok2) ? 0.f : __expf(cS[j*4 + 3] * sc1);
        l1 += p00 + p01;
        l2 += p10 + p11;
        __half ha = __float2half_rn(p00), hb = __float2half_rn(p01);
        __half la = __float2half_rn(p00 - __half2float(ha));
        __half lb = __float2half_rn(p01 - __half2float(hb));
        *(unsigned*)(smem + SM_PHI + r1 * P_STRIDE + jc * 2) = hpair(ha, hb);
        *(unsigned*)(smem + SM_PLO + r1 * P_STRIDE + jc * 2) = hpair(la, lb);
        ha = __float2half_rn(p10); hb = __float2half_rn(p11);
        la = __float2half_rn(p10 - __half2float(ha));
        lb = __float2half_rn(p11 - __half2float(hb));
        *(unsigned*)(smem + SM_PHI + r2 * P_STRIDE + jc * 2) = hpair(ha, hb);
        *(unsigned*)(smem + SM_PLO + r2 * P_STRIDE + jc * 2) = hpair(la, lb);
    }

    l1 += __shfl_xor_sync(0xffffffffu, l1, 1);
    l1 += __shfl_xor_sync(0xffffffffu, l1, 2);
    l2 += __shfl_xor_sync(0xffffffffu, l2, 1);
    l2 += __shfl_xor_sync(0xffffffffu, l2, 2);
    float linv1 = 1.f / l1, linv2 = 1.f / l2;
    if (tg == 0) {
        size_t lbase = (size_t)(b * H + h) * S;
        g_logits[lbase + tok1] = __logf(l1);
        g_logits[lbase + tok2] = __logf(l2);
    }
    __syncwarp();      // P stores visible to own-warp ldmatrix (A reads own rows only)

    // ---------------- MMA2: 2-pass fp16 (V single plane) ----------------
    float oacc[32];
#pragma unroll
    for (int i = 0; i < 32; i++) oacc[i] = 0.f;

    unsigned a2RowOff = (unsigned)((wr + (lane & 15)) * P_STRIDE + (lane >> 4) * 16);
    unsigned vRow = lane & 15, vColHalf = lane >> 4;
#pragma unroll
    for (int ks = 0; ks < 8; ks++) {
        unsigned aaddr = sbase + SM_PHI + a2RowOff + ks * 32;
        unsigned pH0, pH1, pH2, pH3, pL0, pL1, pL2, pL3;
        ldsm4(pH0, pH1, pH2, pH3, aaddr);
        ldsm4(pL0, pL1, pL2, pL3, aaddr + (SM_PLO - SM_PHI));
#pragma unroll
        for (int jp = 0; jp < 4; jp++) {
            unsigned baddr = sbase + SM_VH + (ks * 16 + vRow) * KQ_STRIDE + vColHalf * 16 + jp * 32;
            unsigned vH0, vH1, vH2, vH3;
            ldsm4t(vH0, vH1, vH2, vH3, baddr);
            float* o0 = oacc + (2*jp) * 4;
            float* o1 = oacc + (2*jp + 1) * 4;
            mma_fp16(o0, pH0, pH1, pH2, pH3, vH0, vH1);
            mma_fp16(o0, pL0, pL1, pL2, pL3, vH0, vH1);
            mma_fp16(o1, pH0, pH1, pH2, pH3, vH2, vH3);
            mma_fp16(o1, pL0, pL1, pL2, pL3, vH2, vH3);
        }
    }

    // ---------------- normalize + scatter fp16 (the unsort) ----------------
    __half* orow1 = g_o + (((size_t)(b * H + h) * S + tok1) * D);
    __half* orow2 = g_o + (((size_t)(b * H + h) * S + tok2) * D);
#pragma unroll
    for (int j = 0; j < 8; j++) {
        int col = j * 8 + tg * 2;
        *(unsigned*)(orow1 + col) = hpair(__float2half_rn(oacc[j*4 + 0] * linv1),
                                          __float2half_rn(oacc[j*4 + 1] * linv1));
        *(unsigned*)(orow2 + col) = hpair(__float2half_rn(oacc[j*4 + 2] * linv2),
                                          __float2half_rn(oacc[j*4 + 3] * linv2));
    }
}

// ============================================================
// K4: combine the H rounds.  Warp = 1 token, lane = half2 dim pair.
// ============================================================
__global__ __launch_bounds__(256) void combine_kernel(float* __restrict__ out)
{
    int bt = blockIdx.x * 8 + (threadIdx.x >> 5);
    int b = bt >> 13, t = bt & (S - 1);
    int d2 = threadIdx.x & 31;          // half2 index: dims 2*d2, 2*d2+1

    float lg[H];
    float mx = -INFINITY;
    size_t lbase = ((size_t)b * H) * S + t;
#pragma unroll
    for (int h = 0; h < H; h++) {
        lg[h] = g_logits[lbase + (size_t)h * S];
        mx = fmaxf(mx, lg[h]);
    }
    float sum = 0.f;
#pragma unroll
    for (int h = 0; h < H; h++) { lg[h] = __expf(lg[h] - mx); sum += lg[h]; }

    float a0 = 0.f, a1 = 0.f;
#pragma unroll
    for (int h = 0; h < H; h++) {
        __half2 v = *(const __half2*)(g_o + ((lbase + (size_t)h * S) * D) + 2 * d2);
        float2 vf = __half22float2(v);
        a0 += lg[h] * vf.x;
        a1 += lg[h] * vf.y;
    }

    float inv = 1.f / sum;
    *(float2*)(out + ((size_t)b * S + t) * D + 2 * d2) = make_float2(a0 * inv, a1 * inv);
}

// ============================================================
extern "C" void kernel_launch(void* const* d_in, const int* in_sizes, int n_in,
                              void* d_out, int out_size)
{
    const float* qk  = (const float*)d_in[0];
    const float* v   = (const float*)d_in[1];
    const float* rot = (const float*)d_in[2];
    float* out = (float*)d_out;

    cudaFuncSetAttribute(attn_kernel, cudaFuncAttributeMaxDynamicSharedMemorySize, ATTN_SMEM_B);
    cudaFuncSetAttribute(hash_kernel, cudaFuncAttributeMaxDynamicSharedMemorySize, HASH_SMEM_B);

    hash_kernel<<<dim3(S / 128, H, B), 128, HASH_SMEM_B>>>(qk, rot);
    sort_kernel<<<B * H, 128>>>();
    attn_kernel<<<dim3(CHUNKS, B), 128, ATTN_SMEM_B>>>(qk, v);
    combine_kernel<<<B * S / 8, 256>>>(out);
}

// round 12
// speedup vs baseline: 3.4346x; 1.1811x over previous
#include <cuda_runtime.h>
#include <cuda_bf16.h>
#include <cuda_fp16.h>
#include <math.h>

#define B 8
#define S 8192
#define D 64
#define H 8
#define NB 128
#define BSZ 64
#define CHUNKS 1024

typedef unsigned long long ull;

// ---------- packed f32x2 helpers (sm_100+) ----------
__device__ __forceinline__ ull fma2(ull a, ull b, ull c) {
    ull d; asm("fma.rn.f32x2 %0, %1, %2, %3;" : "=l"(d) : "l"(a), "l"(b), "l"(c)); return d;
}
__device__ __forceinline__ ull pack2(float x, float y) {
    ull r; asm("mov.b64 %0, {%1,%2};" : "=l"(r) : "f"(x), "f"(y)); return r;
}
__device__ __forceinline__ void unpack2(float& x, float& y, ull r) {
    asm("mov.b64 {%0,%1}, %2;" : "=f"(x), "=f"(y) : "l"(r));
}

__device__ __forceinline__ unsigned smem_u32(const void* p) {
    unsigned a; asm("{ .reg .u64 t; cvta.to.shared.u64 t, %1; cvt.u32.u64 %0, t; }" : "=r"(a) : "l"(p));
    return a;
}

// ---------- warp MMA helpers (sm_80+ baseline) ----------
__device__ __forceinline__ void ldsm4(unsigned& r0, unsigned& r1, unsigned& r2, unsigned& r3,
                                      unsigned addr) {
    asm volatile("ldmatrix.sync.aligned.m8n8.x4.shared.b16 {%0,%1,%2,%3}, [%4];"
                 : "=r"(r0), "=r"(r1), "=r"(r2), "=r"(r3) : "r"(addr));
}
__device__ __forceinline__ void ldsm4t(unsigned& r0, unsigned& r1, unsigned& r2, unsigned& r3,
                                       unsigned addr) {
    asm volatile("ldmatrix.sync.aligned.m8n8.x4.trans.shared.b16 {%0,%1,%2,%3}, [%4];"
                 : "=r"(r0), "=r"(r1), "=r"(r2), "=r"(r3) : "r"(addr));
}
__device__ __forceinline__ void mma_fp16(float* c, unsigned a0, unsigned a1, unsigned a2, unsigned a3,
                                         unsigned b0, unsigned b1) {
    asm volatile("mma.sync.aligned.m16n8k16.row.col.f32.f16.f16.f32 "
                 "{%0,%1,%2,%3}, {%4,%5,%6,%7}, {%8,%9}, {%0,%1,%2,%3};"
                 : "+f"(c[0]), "+f"(c[1]), "+f"(c[2]), "+f"(c[3])
                 : "r"(a0), "r"(a1), "r"(a2), "r"(a3), "r"(b0), "r"(b1));
}
__device__ __forceinline__ unsigned hpair(__half a, __half b) {
    __half2 p; p.x = a; p.y = b;
    return *(unsigned*)&p;
}

// -------- device scratch --------
__device__ unsigned char  g_bucket[B * H * S];
__device__ unsigned short g_st[B * H * S];
__device__ float          g_logits[B * H * S];
__device__ __half         g_o[(size_t)B * H * S * D];     // fp16 O
__device__ __half         g_qk16[(size_t)B * S * D];      // fp16 qk
__device__ __half         g_v16[(size_t)B * S * D];       // fp16 v
__device__ float          g_srn[B * S];                   // per-token 0.125/||k||

// ============================================================
// K0: prep — fp16 copies of qk/v + per-token key scale.
// 16 threads per token row (16B each).
// ============================================================
__global__ __launch_bounds__(256) void prep_kernel(const float* __restrict__ qk,
                                                   const float* __restrict__ vin)
{
    int idx = blockIdx.x * 256 + threadIdx.x;
    int tok = idx >> 4;            // global token in [0, B*S)
    int q4 = idx & 15;             // float4 index in row

    float4 f4 = ((const float4*)qk)[(size_t)tok * 16 + q4];
    float ss = f4.x*f4.x + f4.y*f4.y + f4.z*f4.z + f4.w*f4.w;
    ss += __shfl_xor_sync(0xffffffffu, ss, 1);
    ss += __shfl_xor_sync(0xffffffffu, ss, 2);
    ss += __shfl_xor_sync(0xffffffffu, ss, 4);
    ss += __shfl_xor_sync(0xffffffffu, ss, 8);
    if (q4 == 0)
        g_srn[tok] = 0.125f / fmaxf(sqrtf(ss), 1e-12f);

    uint2 kp;
    kp.x = hpair(__float2half_rn(f4.x), __float2half_rn(f4.y));
    kp.y = hpair(__float2half_rn(f4.z), __float2half_rn(f4.w));
    *(uint2*)(g_qk16 + (size_t)tok * D + q4 * 4) = kp;

    float4 v4 = ((const float4*)vin)[(size_t)tok * 16 + q4];
    uint2 vp;
    vp.x = hpair(__float2half_rn(v4.x), __float2half_rn(v4.y));
    vp.y = hpair(__float2half_rn(v4.z), __float2half_rn(v4.w));
    *(uint2*)(g_v16 + (size_t)tok * D + q4 * 4) = vp;
}

// ============================================================
// K1: LSH hashing (fp32 — argmax stability requires it).
// ============================================================
#define HQ_STRIDE 132
#define HASH_SMEM_B 58368

__global__ __launch_bounds__(128) void hash_kernel(const float* __restrict__ qk,
                                                   const float* __restrict__ rot)
{
    extern __shared__ float hsm[];
    float* srot = hsm;                    // [f*64 + i]
    float* sqT  = hsm + 4096;             // [f*132 + tok]
    float* sPv  = hsm + 12544;            // [g*128 + tok]
    float* sNv  = hsm + 13056;
    int*   sPi  = (int*)(hsm + 13568);
    int*   sNi  = (int*)(hsm + 14080);

    int b = blockIdx.z, h = blockIdx.y, tile = blockIdx.x;
    int tid = threadIdx.x;

    for (int idx = tid; idx < 64 * 64; idx += 128) {
        int f = idx >> 6, i = idx & 63;
        srot[idx] = rot[(size_t)f * (H * 64) + h * 64 + i];
    }
    int t0 = tile * 128;
    {
        const float4* qr = (const float4*)(qk + ((size_t)b * S + t0 + tid) * D);
#pragma unroll
        for (int i = 0; i < 16; i++) {
            float4 f4 = qr[i];
            sqT[(4*i + 0) * HQ_STRIDE + tid] = f4.x;
            sqT[(4*i + 1) * HQ_STRIDE + tid] = f4.y;
            sqT[(4*i + 2) * HQ_STRIDE + tid] = f4.z;
            sqT[(4*i + 3) * HQ_STRIDE + tid] = f4.w;
        }
    }
    __syncthreads();

    int g = tid >> 5, lane = tid & 31;
    ull acc[32];
#pragma unroll
    for (int i = 0; i < 32; i++) acc[i] = 0ull;

    const float* rbase = srot + g * 16;
    const float* qbase = sqT + lane * 4;
    for (int f = 0; f < 64; f++) {
        const ulonglong2* rp = (const ulonglong2*)(rbase + f * 64);
        ulonglong2 u0 = rp[0], u1 = rp[1];
        float4 q4 = *(const float4*)(qbase + f * HQ_STRIDE);
        ull rr[4] = { u0.x, u0.y, u1.x, u1.y };
        float qa[4] = { q4.x, q4.y, q4.z, q4.w };
#pragma unroll
        for (int tt = 0; tt < 4; tt++) {
            ull qq = pack2(qa[tt], qa[tt]);
#pragma unroll
            for (int i = 0; i < 4; i++)
                acc[tt*8 + i] = fma2(qq, rr[i], acc[tt*8 + i]);
        }
        const ulonglong2* rp2 = (const ulonglong2*)(rbase + f * 64 + 8);
        ulonglong2 u2 = rp2[0], u3 = rp2[1];
        ull rr2[4] = { u2.x, u2.y, u3.x, u3.y };
#pragma unroll
        for (int tt = 0; tt < 4; tt++) {
            ull qq = pack2(qa[tt], qa[tt]);
#pragma unroll
            for (int i = 0; i < 4; i++)
                acc[tt*8 + 4 + i] = fma2(qq, rr2[i], acc[tt*8 + 4 + i]);
        }
    }

#pragma unroll
    for (int tt = 0; tt < 4; tt++) {
        float bestP = -INFINITY, bestN = -INFINITY;
        int ip = 0, inn = 0;
#pragma unroll
        for (int i = 0; i < 8; i++) {
            float lo, hi; unpack2(lo, hi, acc[tt*8 + i]);
            int col = g * 16 + 2 * i;
            if (lo > bestP)  { bestP = lo;  ip  = col;     }
            if (hi > bestP)  { bestP = hi;  ip  = col + 1; }
            if (-lo > bestN) { bestN = -lo; inn = col;     }
            if (-hi > bestN) { bestN = -hi; inn = col + 1; }
        }
        int tok = lane * 4 + tt;
        sPv[g * 128 + tok] = bestP; sPi[g * 128 + tok] = ip;
        sNv[g * 128 + tok] = bestN; sNi[g * 128 + tok] = inn;
    }
    __syncthreads();

    {
        float bestP = sPv[tid], bestN = sNv[tid];
        int ip = sPi[tid], inn = sNi[tid];
#pragma unroll
        for (int gg = 1; gg < 4; gg++) {
            float v = sPv[gg * 128 + tid];
            if (v > bestP) { bestP = v; ip = sPi[gg * 128 + tid]; }
            float w = sNv[gg * 128 + tid];
            if (w > bestN) { bestN = w; inn = sNi[gg * 128 + tid]; }
        }
        int bucket = (bestP >= bestN) ? ip : (64 + inn);
        g_bucket[((size_t)b * H + h) * S + t0 + tid] = (unsigned char)bucket;
    }
}

// ============================================================
// K2: stable counting sort per (b,h)
// ============================================================
__global__ __launch_bounds__(128) void sort_kernel()
{
    int bh = blockIdx.x;
    __shared__ unsigned char sb[S];
    __shared__ int hist[NB];
    __shared__ int base[NB];
    int tid = threadIdx.x;

    hist[tid] = 0;
    __syncthreads();

    const uchar4* src = (const uchar4*)(g_bucket + (size_t)bh * S);
    for (int i = tid; i < S / 4; i += 128) {
        uchar4 u = src[i];
        ((uchar4*)sb)[i] = u;
        atomicAdd(&hist[u.x], 1);
        atomicAdd(&hist[u.y], 1);
        atomicAdd(&hist[u.z], 1);
        atomicAdd(&hist[u.w], 1);
    }
    __syncthreads();

    if (tid == 0) {
        int s = 0;
        for (int k = 0; k < NB; k++) { base[k] = s; s += hist[k]; }
    }
    __syncthreads();

    int myb = tid;
    int cnt = base[myb];
    unsigned short* dst = g_st + (size_t)bh * S;
    for (int i = 0; i < S; i += 4) {
        uchar4 u = *(const uchar4*)(sb + i);
        if (u.x == myb) dst[cnt++] = (unsigned short)(i);
        if (u.y == myb) dst[cnt++] = (unsigned short)(i + 1);
        if (u.z == myb) dst[cnt++] = (unsigned short)(i + 2);
        if (u.w == myb) dst[cnt++] = (unsigned short)(i + 3);
    }
}

// ============================================================
// K3: mma.sync attention v6.
//  - staging gathers PRECONVERTED fp16 rows (g_qk16/g_v16):
//    warp loads 4 rows/instr (8 lanes x 16B), pure LDG->STS
//  - srn / conversions hoisted to prep kernel
//  - MMA1 single-pass fp16; MMA2 fp16 2-pass; O fp16
//
// smem bytes:
//   0      skid[128]        512 srn[128]
//   1024   KQ fp16 128x72 (18432)  [Phi fp16 64x136 = 17408 aliases]
//   19456  Plo fp16 64x136 (17408)
//   36864  V  fp16 128x72 (18432)  total 55296
// ============================================================
#define SM_SKID 0
#define SM_SRN  512
#define SM_KQ   1024
#define SM_PHI  1024
#define SM_PLO  19456
#define SM_VH   36864
#define ATTN_SMEM_B 55296
#define KQ_STRIDE 144     // bytes (72 fp16)
#define P_STRIDE  272     // bytes (136 fp16)

__global__ __launch_bounds__(128) void attn_kernel()
{
    extern __shared__ char smem[];
    unsigned sbase = smem_u32(smem);
    int tid = threadIdx.x;
    int b = blockIdx.y, c = blockIdx.x, h = c >> 7;
    int* skid = (int*)(smem + SM_SKID);
    float* srn_s = (float*)(smem + SM_SRN);

    int lane = tid & 31, warp = tid >> 5;

    // ---------------- staging: coalesced fp16 gather ----------------
    int kt;
    {
        int slot = tid;
        int kc = (slot < 64) ? c : ((c + CHUNKS - 1) & (CHUNKS - 1));
        const unsigned short* ST = g_st + (size_t)b * (H * S);
        kt = ST[kc * BSZ + (slot & 63)];
        skid[slot] = kt;
        srn_s[slot] = g_srn[b * S + kt];

        int sub = lane >> 3;        // which of 4 rows this lane serves
        int q8 = lane & 7;          // uint4 (16B) index within fp16 row
        const size_t brow = (size_t)b * S;

#pragma unroll
        for (int it = 0; it < 8; it++) {
            int s2 = warp * 32 + it * 4 + sub;
            int tok = __shfl_sync(0xffffffffu, kt, it * 4 + sub);
            uint4 kk = ((const uint4*)(g_qk16 + (brow + tok) * D))[q8];
            *(uint4*)(smem + SM_KQ + s2 * KQ_STRIDE + q8 * 16) = kk;
            uint4 vv = ((const uint4*)(g_v16 + (brow + tok) * D))[q8];
            *(uint4*)(smem + SM_VH + s2 * KQ_STRIDE + q8 * 16) = vv;
        }
    }
    __syncthreads();

    int wr = warp * 16;
    int g = lane >> 2, tg = lane & 3;

    unsigned aRowOff = (unsigned)((wr + (lane & 15)) * KQ_STRIDE + (lane >> 4) * 16);
    unsigned bn  = (lane & 7) + ((lane >> 4) << 3);
    unsigned bkh = (lane >> 3) & 1;

    // ---------------- MMA1: single-pass fp16 ----------------
    float cS[64];
#pragma unroll
    for (int i = 0; i < 64; i++) cS[i] = 0.f;

#pragma unroll
    for (int ks = 0; ks < 4; ks++) {
        unsigned aaddr = sbase + SM_KQ + aRowOff + ks * 32;
        unsigned aH0, aH1, aH2, aH3;
        ldsm4(aH0, aH1, aH2, aH3, aaddr);
#pragma unroll
        for (int jp = 0; jp < 8; jp++) {
            unsigned baddr = sbase + SM_KQ + (jp * 16 + bn) * KQ_STRIDE + bkh * 16 + ks * 32;
            unsigned bH0, bH1, bH2, bH3;
            ldsm4(bH0, bH1, bH2, bH3, baddr);
            mma_fp16(cS + (2*jp) * 4,     aH0, aH1, aH2, aH3, bH0, bH1);
            mma_fp16(cS + (2*jp + 1) * 4, aH0, aH1, aH2, aH3, bH2, bH3);
        }
    }

    // ---------------- epilogue: scale + mask + exp + fp16 P split ----------------
    int r1 = wr + g, r2 = r1 + 8;
    int tok1 = skid[r1], tok2 = skid[r2];
    float l1 = 0.f, l2 = 0.f;

    __syncthreads();   // all warps done reading KQ before P overwrites it

#pragma unroll
    for (int j = 0; j < 16; j++) {
        int jc = j * 8 + tg * 2;
        int kid0 = skid[jc], kid1 = skid[jc + 1];
        float sc0 = srn_s[jc], sc1 = srn_s[jc + 1];
        float p00 = (kid0 == tok1) ? 0.f : __expf(cS[j*4 + 0] * sc0);
        float p01 = (kid1 == tok1) ? 0.f : __expf(cS[j*4 + 1] * sc1);
        float p10 = (kid0 == tok2) ? 0.f : __expf(cS[j*4 + 2] * sc0);
        float p11 = (kid1 == tok2) ? 0.f : __expf(cS[j*4 + 3] * sc1);
        l1 += p00 + p01;
        l2 += p10 + p11;
        __half ha = __float2half_rn(p00), hb = __float2half_rn(p01);
        __half la = __float2half_rn(p00 - __half2float(ha));
        __half lb = __float2half_rn(p01 - __half2float(hb));
        *(unsigned*)(smem + SM_PHI + r1 * P_STRIDE + jc * 2) = hpair(ha, hb);
        *(unsigned*)(smem + SM_PLO + r1 * P_STRIDE + jc * 2) = hpair(la, lb);
        ha = __float2half_rn(p10); hb = __float2half_rn(p11);
        la = __float2half_rn(p10 - __half2float(ha));
        lb = __float2half_rn(p11 - __half2float(hb));
        *(unsigned*)(smem + SM_PHI + r2 * P_STRIDE + jc * 2) = hpair(ha, hb);
        *(unsigned*)(smem + SM_PLO + r2 * P_STRIDE + jc * 2) = hpair(la, lb);
    }

    l1 += __shfl_xor_sync(0xffffffffu, l1, 1);
    l1 += __shfl_xor_sync(0xffffffffu, l1, 2);
    l2 += __shfl_xor_sync(0xffffffffu, l2, 1);
    l2 += __shfl_xor_sync(0xffffffffu, l2, 2);
    float linv1 = 1.f / l1, linv2 = 1.f / l2;
    if (tg == 0) {
        size_t lbase = (size_t)(b * H + h) * S;
        g_logits[lbase + tok1] = __logf(l1);
        g_logits[lbase + tok2] = __logf(l2);
    }
    __syncwarp();      // P stores visible to own-warp ldmatrix (A reads own rows only)

    // ---------------- MMA2: 2-pass fp16 (V single plane) ----------------
    float oacc[32];
#pragma unroll
    for (int i = 0; i < 32; i++) oacc[i] = 0.f;

    unsigned a2RowOff = (unsigned)((wr + (lane & 15)) * P_STRIDE + (lane >> 4) * 16);
    unsigned vRow = lane & 15, vColHalf = lane >> 4;
#pragma unroll
    for (int ks = 0; ks < 8; ks++) {
        unsigned aaddr = sbase + SM_PHI + a2RowOff + ks * 32;
        unsigned pH0, pH1, pH2, pH3, pL0, pL1, pL2, pL3;
        ldsm4(pH0, pH1, pH2, pH3, aaddr);
        ldsm4(pL0, pL1, pL2, pL3, aaddr + (SM_PLO - SM_PHI));
#pragma unroll
        for (int jp = 0; jp < 4; jp++) {
            unsigned baddr = sbase + SM_VH + (ks * 16 + vRow) * KQ_STRIDE + vColHalf * 16 + jp * 32;
            unsigned vH0, vH1, vH2, vH3;
            ldsm4t(vH0, vH1, vH2, vH3, baddr);
            float* o0 = oacc + (2*jp) * 4;
            float* o1 = oacc + (2*jp + 1) * 4;
            mma_fp16(o0, pH0, pH1, pH2, pH3, vH0, vH1);
            mma_fp16(o0, pL0, pL1, pL2, pL3, vH0, vH1);
            mma_fp16(o1, pH0, pH1, pH2, pH3, vH2, vH3);
            mma_fp16(o1, pL0, pL1, pL2, pL3, vH2, vH3);
        }
    }

    // ---------------- normalize + scatter fp16 (the unsort) ----------------
    __half* orow1 = g_o + (((size_t)(b * H + h) * S + tok1) * D);
    __half* orow2 = g_o + (((size_t)(b * H + h) * S + tok2) * D);
#pragma unroll
    for (int j = 0; j < 8; j++) {
        int col = j * 8 + tg * 2;
        *(unsigned*)(orow1 + col) = hpair(__float2half_rn(oacc[j*4 + 0] * linv1),
                                          __float2half_rn(oacc[j*4 + 1] * linv1));
        *(unsigned*)(orow2 + col) = hpair(__float2half_rn(oacc[j*4 + 2] * linv2),
                                          __float2half_rn(oacc[j*4 + 3] * linv2));
    }
}

// ============================================================
// K4: combine the H rounds.  Warp = 1 token, lane = half2 dim pair.
// ============================================================
__global__ __launch_bounds__(256) void combine_kernel(float* __restrict__ out)
{
    int bt = blockIdx.x * 8 + (threadIdx.x >> 5);
    int b = bt >> 13, t = bt & (S - 1);
    int d2 = threadIdx.x & 31;          // half2 index: dims 2*d2, 2*d2+1

    float lg[H];
    float mx = -INFINITY;
    size_t lbase = ((size_t)b * H) * S + t;
#pragma unroll
    for (int h = 0; h < H; h++) {
        lg[h] = g_logits[lbase + (size_t)h * S];
        mx = fmaxf(mx, lg[h]);
    }
    float sum = 0.f;
#pragma unroll
    for (int h = 0; h < H; h++) { lg[h] = __expf(lg[h] - mx); sum += lg[h]; }

    float a0 = 0.f, a1 = 0.f;
#pragma unroll
    for (int h = 0; h < H; h++) {
        __half2 v = *(const __half2*)(g_o + ((lbase + (size_t)h * S) * D) + 2 * d2);
        float2 vf = __half22float2(v);
        a0 += lg[h] * vf.x;
        a1 += lg[h] * vf.y;
    }

    float inv = 1.f / sum;
    *(float2*)(out + ((size_t)b * S + t) * D + 2 * d2) = make_float2(a0 * inv, a1 * inv);
}

// ============================================================
extern "C" void kernel_launch(void* const* d_in, const int* in_sizes, int n_in,
                              void* d_out, int out_size)
{
    const float* qk  = (const float*)d_in[0];
    const float* v   = (const float*)d_in[1];
    const float* rot = (const float*)d_in[2];
    float* out = (float*)d_out;

    cudaFuncSetAttribute(attn_kernel, cudaFuncAttributeMaxDynamicSharedMemorySize, ATTN_SMEM_B);
    cudaFuncSetAttribute(hash_kernel, cudaFuncAttributeMaxDynamicSharedMemorySize, HASH_SMEM_B);

    prep_kernel<<<B * S * 16 / 256, 256>>>(qk, v);
    hash_kernel<<<dim3(S / 128, H, B), 128, HASH_SMEM_B>>>(qk, rot);
    sort_kernel<<<B * H, 128>>>();
    attn_kernel<<<dim3(CHUNKS, B), 128, ATTN_SMEM_B>>>();
    combine_kernel<<<B * S / 8, 256>>>(out);
}

// round 14
// speedup vs baseline: 3.8119x; 1.1099x over previous
#include <cuda_runtime.h>
#include <cuda_bf16.h>
#include <cuda_fp16.h>
#include <math.h>

#define B 8
#define S 8192
#define D 64
#define H 8
#define NB 128
#define BSZ 64
#define CHUNKS 1024

typedef unsigned long long ull;

// ---------- packed f32x2 helpers (sm_100+) ----------
__device__ __forceinline__ ull fma2(ull a, ull b, ull c) {
    ull d; asm("fma.rn.f32x2 %0, %1, %2, %3;" : "=l"(d) : "l"(a), "l"(b), "l"(c)); return d;
}
__device__ __forceinline__ ull pack2(float x, float y) {
    ull r; asm("mov.b64 %0, {%1,%2};" : "=l"(r) : "f"(x), "f"(y)); return r;
}
__device__ __forceinline__ void unpack2(float& x, float& y, ull r) {
    asm("mov.b64 {%0,%1}, %2;" : "=f"(x), "=f"(y) : "l"(r));
}

__device__ __forceinline__ unsigned smem_u32(const void* p) {
    unsigned a; asm("{ .reg .u64 t; cvta.to.shared.u64 t, %1; cvt.u32.u64 %0, t; }" : "=r"(a) : "l"(p));
    return a;
}

// ---------- warp MMA helpers (sm_80+ baseline) ----------
__device__ __forceinline__ void ldsm4(unsigned& r0, unsigned& r1, unsigned& r2, unsigned& r3,
                                      unsigned addr) {
    asm volatile("ldmatrix.sync.aligned.m8n8.x4.shared.b16 {%0,%1,%2,%3}, [%4];"
                 : "=r"(r0), "=r"(r1), "=r"(r2), "=r"(r3) : "r"(addr));
}
__device__ __forceinline__ void ldsm4t(unsigned& r0, unsigned& r1, unsigned& r2, unsigned& r3,
                                       unsigned addr) {
    asm volatile("ldmatrix.sync.aligned.m8n8.x4.trans.shared.b16 {%0,%1,%2,%3}, [%4];"
                 : "=r"(r0), "=r"(r1), "=r"(r2), "=r"(r3) : "r"(addr));
}
__device__ __forceinline__ void mma_fp16(float* c, unsigned a0, unsigned a1, unsigned a2, unsigned a3,
                                         unsigned b0, unsigned b1) {
    asm volatile("mma.sync.aligned.m16n8k16.row.col.f32.f16.f16.f32 "
                 "{%0,%1,%2,%3}, {%4,%5,%6,%7}, {%8,%9}, {%0,%1,%2,%3};"
                 : "+f"(c[0]), "+f"(c[1]), "+f"(c[2]), "+f"(c[3])
                 : "r"(a0), "r"(a1), "r"(a2), "r"(a3), "r"(b0), "r"(b1));
}
__device__ __forceinline__ unsigned hpair(__half a, __half b) {
    __half2 p; p.x = a; p.y = b;
    return *(unsigned*)&p;
}

// -------- device scratch --------
__device__ unsigned char  g_bucket[B * H * S];
__device__ unsigned short g_st[B * H * S];
__device__ float          g_logits[B * H * S];
__device__ __half         g_o[(size_t)B * H * S * D];     // fp16 O
__device__ __half         g_qk16[(size_t)B * S * D];      // fp16 qk
__device__ __half         g_v16[(size_t)B * S * D];       // fp16 v
__device__ float          g_srn[B * S];                   // per-token 0.125/||k||

// ============================================================
// K0: prep — fp16 copies of qk/v + per-token key scale.
// ============================================================
__global__ __launch_bounds__(256) void prep_kernel(const float* __restrict__ qk,
                                                   const float* __restrict__ vin)
{
    int idx = blockIdx.x * 256 + threadIdx.x;
    int tok = idx >> 4;
    int q4 = idx & 15;

    float4 f4 = ((const float4*)qk)[(size_t)tok * 16 + q4];
    float ss = f4.x*f4.x + f4.y*f4.y + f4.z*f4.z + f4.w*f4.w;
    ss += __shfl_xor_sync(0xffffffffu, ss, 1);
    ss += __shfl_xor_sync(0xffffffffu, ss, 2);
    ss += __shfl_xor_sync(0xffffffffu, ss, 4);
    ss += __shfl_xor_sync(0xffffffffu, ss, 8);
    if (q4 == 0)
        g_srn[tok] = 0.125f / fmaxf(sqrtf(ss), 1e-12f);

    uint2 kp;
    kp.x = hpair(__float2half_rn(f4.x), __float2half_rn(f4.y));
    kp.y = hpair(__float2half_rn(f4.z), __float2half_rn(f4.w));
    *(uint2*)(g_qk16 + (size_t)tok * D + q4 * 4) = kp;

    float4 v4 = ((const float4*)vin)[(size_t)tok * 16 + q4];
    uint2 vp;
    vp.x = hpair(__float2half_rn(v4.x), __float2half_rn(v4.y));
    vp.y = hpair(__float2half_rn(v4.z), __float2half_rn(v4.w));
    *(uint2*)(g_v16 + (size_t)tok * D + q4 * 4) = vp;
}

// ============================================================
// K1: LSH hashing (fp32).  2 tokens/thread, two half-passes —
// acc[16] keeps registers ~70, no spills.
// ============================================================
#define HQ_STRIDE 132
#define HASH_SMEM_B 58368

__global__ __launch_bounds__(128) void hash_kernel(const float* __restrict__ qk,
                                                   const float* __restrict__ rot)
{
    extern __shared__ float hsm[];
    float* srot = hsm;                    // [f*64 + i]
    float* sqT  = hsm + 4096;             // [f*132 + tok]
    float* sPv  = hsm + 12544;            // [g*128 + tok]
    float* sNv  = hsm + 13056;
    int*   sPi  = (int*)(hsm + 13568);
    int*   sNi  = (int*)(hsm + 14080);

    int b = blockIdx.z, h = blockIdx.y, tile = blockIdx.x;
    int tid = threadIdx.x;

    for (int idx = tid; idx < 64 * 64; idx += 128) {
        int f = idx >> 6, i = idx & 63;
        srot[idx] = rot[(size_t)f * (H * 64) + h * 64 + i];
    }
    int t0 = tile * 128;
    {
        const float4* qr = (const float4*)(qk + ((size_t)b * S + t0 + tid) * D);
#pragma unroll
        for (int i = 0; i < 16; i++) {
            float4 f4 = qr[i];
            sqT[(4*i + 0) * HQ_STRIDE + tid] = f4.x;
            sqT[(4*i + 1) * HQ_STRIDE + tid] = f4.y;
            sqT[(4*i + 2) * HQ_STRIDE + tid] = f4.z;
            sqT[(4*i + 3) * HQ_STRIDE + tid] = f4.w;
        }
    }
    __syncthreads();

    int g = tid >> 5, lane = tid & 31;
    const float* rbase = srot + g * 16;

    for (int hp = 0; hp < 2; hp++) {
        int tok0 = hp * 64 + lane * 2;         // this thread: tokens tok0, tok0+1
        ull acc[16];
#pragma unroll
        for (int i = 0; i < 16; i++) acc[i] = 0ull;

        const float* qbase = sqT + tok0;
        for (int f = 0; f < 64; f++) {
            const ulonglong2* rp = (const ulonglong2*)(rbase + f * 64);
            ulonglong2 u0 = rp[0], u1 = rp[1];
            const ulonglong2* rp2 = (const ulonglong2*)(rbase + f * 64 + 8);
            ulonglong2 u2 = rp2[0], u3 = rp2[1];
            float2 q2 = *(const float2*)(qbase + f * HQ_STRIDE);
            ull rr[8] = { u0.x, u0.y, u1.x, u1.y, u2.x, u2.y, u3.x, u3.y };
            ull qq0 = pack2(q2.x, q2.x);
            ull qq1 = pack2(q2.y, q2.y);
#pragma unroll
            for (int i = 0; i < 8; i++) {
                acc[i]     = fma2(qq0, rr[i], acc[i]);
                acc[8 + i] = fma2(qq1, rr[i], acc[8 + i]);
            }
        }

#pragma unroll
        for (int tt = 0; tt < 2; tt++) {
            float bestP = -INFINITY, bestN = -INFINITY;
            int ip = 0, inn = 0;
#pragma unroll
            for (int i = 0; i < 8; i++) {
                float lo, hi; unpack2(lo, hi, acc[tt*8 + i]);
                int col = g * 16 + 2 * i;
                if (lo > bestP)  { bestP = lo;  ip  = col;     }
                if (hi > bestP)  { bestP = hi;  ip  = col + 1; }
                if (-lo > bestN) { bestN = -lo; inn = col;     }
                if (-hi > bestN) { bestN = -hi; inn = col + 1; }
            }
            int tok = tok0 + tt;
            sPv[g * 128 + tok] = bestP; sPi[g * 128 + tok] = ip;
            sNv[g * 128 + tok] = bestN; sNi[g * 128 + tok] = inn;
        }
    }
    __syncthreads();

    {
        float bestP = sPv[tid], bestN = sNv[tid];
        int ip = sPi[tid], inn = sNi[tid];
#pragma unroll
        for (int gg = 1; gg < 4; gg++) {
            float v = sPv[gg * 128 + tid];
            if (v > bestP) { bestP = v; ip = sPi[gg * 128 + tid]; }
            float w = sNv[gg * 128 + tid];
            if (w > bestN) { bestN = w; inn = sNi[gg * 128 + tid]; }
        }
        int bucket = (bestP >= bestN) ? ip : (64 + inn);
        g_bucket[((size_t)b * H + h) * S + t0 + tid] = (unsigned char)bucket;
    }
}

// ============================================================
// K2: stable counting sort, 256 threads, 2 segments per bucket.
// ============================================================
__global__ __launch_bounds__(256) void sort_kernel()
{
    int bh = blockIdx.x;
    __shared__ unsigned char sb[S];
    __shared__ int histA[NB];   // tokens [0, 4096)
    __shared__ int histB[NB];   // tokens [4096, 8192)
    __shared__ int base[NB];
    int tid = threadIdx.x;

    if (tid < NB) { histA[tid] = 0; histB[tid] = 0; }
    __syncthreads();

    const uchar4* src = (const uchar4*)(g_bucket + (size_t)bh * S);
    for (int i = tid; i < S / 4; i += 256) {
        uchar4 u = src[i];
        ((uchar4*)sb)[i] = u;
        int* hist = (i < S / 8) ? histA : histB;
        atomicAdd(&hist[u.x], 1);
        atomicAdd(&hist[u.y], 1);
        atomicAdd(&hist[u.z], 1);
        atomicAdd(&hist[u.w], 1);
    }
    __syncthreads();

    if (tid == 0) {
        int s = 0;
        for (int k = 0; k < NB; k++) { base[k] = s; s += histA[k] + histB[k]; }
    }
    __syncthreads();

    int myb = tid & 127;
    int seg = tid >> 7;                // 0: first half, 1: second half
    int cnt = base[myb] + (seg ? histA[myb] : 0);
    int i0 = seg ? S / 2 : 0;
    int i1 = i0 + S / 2;
    unsigned short* dst = g_st + (size_t)bh * S;
    for (int i = i0; i < i1; i += 4) {
        uchar4 u = *(const uchar4*)(sb + i);
        if (u.x == myb) dst[cnt++] = (unsigned short)(i);
        if (u.y == myb) dst[cnt++] = (unsigned short)(i + 1);
        if (u.z == myb) dst[cnt++] = (unsigned short)(i + 2);
        if (u.w == myb) dst[cnt++] = (unsigned short)(i + 3);
    }
}

// ============================================================
// K3: mma.sync attention v7 — register-resident P (FA2 trick).
// MMA1 fp32 C-fragment layout == MMA2 A-fragment layout, so
// exp(p) hi/lo fp16 pairs are assembled in registers; no P smem,
// no post-MMA1 sync, 35KB less smem.
//
// smem bytes:
//   0      skid[128] (512)   512 srn[128] (512)
//   1024   KQ fp16 128x72 (18432)
//   19456  V  fp16 128x72 (18432)   total 37888
// ============================================================
#define SM_SKID 0
#define SM_SRN  512
#define SM_KQ   1024
#define SM_VH   19456
#define ATTN_SMEM_B 37888
#define KQ_STRIDE 144     // bytes (72 fp16)

__global__ __launch_bounds__(128) void attn_kernel()
{
    extern __shared__ char smem[];
    unsigned sbase = smem_u32(smem);
    int tid = threadIdx.x;
    int b = blockIdx.y, c = blockIdx.x, h = c >> 7;
    int* skid = (int*)(smem + SM_SKID);
    float* srn_s = (float*)(smem + SM_SRN);

    int lane = tid & 31, warp = tid >> 5;

    // ---------------- staging: coalesced fp16 gather ----------------
    {
        int slot = tid;
        int kc = (slot < 64) ? c : ((c + CHUNKS - 1) & (CHUNKS - 1));
        const unsigned short* ST = g_st + (size_t)b * (H * S);
        int kt = ST[kc * BSZ + (slot & 63)];
        skid[slot] = kt;
        srn_s[slot] = g_srn[b * S + kt];

        int sub = lane >> 3;
        int q8 = lane & 7;
        const size_t brow = (size_t)b * S;

#pragma unroll
        for (int it = 0; it < 8; it++) {
            int s2 = warp * 32 + it * 4 + sub;
            int tok = __shfl_sync(0xffffffffu, kt, it * 4 + sub);
            uint4 kk = ((const uint4*)(g_qk16 + (brow + tok) * D))[q8];
            *(uint4*)(smem + SM_KQ + s2 * KQ_STRIDE + q8 * 16) = kk;
            uint4 vv = ((const uint4*)(g_v16 + (brow + tok) * D))[q8];
            *(uint4*)(smem + SM_VH + s2 * KQ_STRIDE + q8 * 16) = vv;
        }
    }
    __syncthreads();

    int wr = warp * 16;
    int g = lane >> 2, tg = lane & 3;

    unsigned aRowOff = (unsigned)((wr + (lane & 15)) * KQ_STRIDE + (lane >> 4) * 16);
    unsigned bn  = (lane & 7) + ((lane >> 4) << 3);
    unsigned bkh = (lane >> 3) & 1;

    // ---------------- MMA1: single-pass fp16 ----------------
    float cS[64];
#pragma unroll
    for (int i = 0; i < 64; i++) cS[i] = 0.f;

#pragma unroll
    for (int ks = 0; ks < 4; ks++) {
        unsigned aaddr = sbase + SM_KQ + aRowOff + ks * 32;
        unsigned aH0, aH1, aH2, aH3;
        ldsm4(aH0, aH1, aH2, aH3, aaddr);
#pragma unroll
        for (int jp = 0; jp < 8; jp++) {
            unsigned baddr = sbase + SM_KQ + (jp * 16 + bn) * KQ_STRIDE + bkh * 16 + ks * 32;
            unsigned bH0, bH1, bH2, bH3;
            ldsm4(bH0, bH1, bH2, bH3, baddr);
            mma_fp16(cS + (2*jp) * 4,     aH0, aH1, aH2, aH3, bH0, bH1);
            mma_fp16(cS + (2*jp + 1) * 4, aH0, aH1, aH2, aH3, bH2, bH3);
        }
    }

    // ---------------- epilogue: mask + exp -> register A-fragments ----------------
    int r1 = wr + g, r2 = r1 + 8;
    int tok1 = skid[r1], tok2 = skid[r2];
    float l1 = 0.f, l2 = 0.f;

    unsigned pHi[32], pLo[32];     // MMA2 A-fragments: [ks*4 + slot]
#pragma unroll
    for (int j = 0; j < 16; j++) {
        int jc = j * 8 + tg * 2;
        int kid0 = skid[jc], kid1 = skid[jc + 1];
        float sc0 = srn_s[jc], sc1 = srn_s[jc + 1];
        float p00 = (kid0 == tok1) ? 0.f : __expf(cS[j*4 + 0] * sc0);
        float p01 = (kid1 == tok1) ? 0.f : __expf(cS[j*4 + 1] * sc1);
        float p10 = (kid0 == tok2) ? 0.f : __expf(cS[j*4 + 2] * sc0);
        float p11 = (kid1 == tok2) ? 0.f : __expf(cS[j*4 + 3] * sc1);
        l1 += p00 + p01;
        l2 += p10 + p11;
        __half h00 = __float2half_rn(p00), h01 = __float2half_rn(p01);
        __half h10 = __float2half_rn(p10), h11 = __float2half_rn(p11);
        int slot = (j >> 1) * 4 + (j & 1) * 2;   // even j -> a0,a1; odd j -> a2,a3
        pHi[slot]     = hpair(h00, h01);
        pHi[slot + 1] = hpair(h10, h11);
        pLo[slot]     = hpair(__float2half_rn(p00 - __half2float(h00)),
                              __float2half_rn(p01 - __half2float(h01)));
        pLo[slot + 1] = hpair(__float2half_rn(p10 - __half2float(h10)),
                              __float2half_rn(p11 - __half2float(h11)));
    }

    l1 += __shfl_xor_sync(0xffffffffu, l1, 1);
    l1 += __shfl_xor_sync(0xffffffffu, l1, 2);
    l2 += __shfl_xor_sync(0xffffffffu, l2, 1);
    l2 += __shfl_xor_sync(0xffffffffu, l2, 2);
    float linv1 = 1.f / l1, linv2 = 1.f / l2;
    if (tg == 0) {
        size_t lbase = (size_t)(b * H + h) * S;
        g_logits[lbase + tok1] = __logf(l1);
        g_logits[lbase + tok2] = __logf(l2);
    }

    // ---------------- MMA2: 2-pass fp16, A from registers ----------------
    float oacc[32];
#pragma unroll
    for (int i = 0; i < 32; i++) oacc[i] = 0.f;

    unsigned vRow = lane & 15, vColHalf = lane >> 4;
#pragma unroll
    for (int ks = 0; ks < 8; ks++) {
        unsigned pH0 = pHi[ks*4], pH1 = pHi[ks*4+1], pH2 = pHi[ks*4+2], pH3 = pHi[ks*4+3];
        unsigned pL0 = pLo[ks*4], pL1 = pLo[ks*4+1], pL2 = pLo[ks*4+2], pL3 = pLo[ks*4+3];
#pragma unroll
        for (int jp = 0; jp < 4; jp++) {
            unsigned baddr = sbase + SM_VH + (ks * 16 + vRow) * KQ_STRIDE + vColHalf * 16 + jp * 32;
            unsigned vH0, vH1, vH2, vH3;
            ldsm4t(vH0, vH1, vH2, vH3, baddr);
            float* o0 = oacc + (2*jp) * 4;
            float* o1 = oacc + (2*jp + 1) * 4;
            mma_fp16(o0, pH0, pH1, pH2, pH3, vH0, vH1);
            mma_fp16(o0, pL0, pL1, pL2, pL3, vH0, vH1);
            mma_fp16(o1, pH0, pH1, pH2, pH3, vH2, vH3);
            mma_fp16(o1, pL0, pL1, pL2, pL3, vH2, vH3);
        }
    }

    // ---------------- normalize + scatter fp16 (the unsort) ----------------
    __half* orow1 = g_o + (((size_t)(b * H + h) * S + tok1) * D);
    __half* orow2 = g_o + (((size_t)(b * H + h) * S + tok2) * D);
#pragma unroll
    for (int j = 0; j < 8; j++) {
        int col = j * 8 + tg * 2;
        *(unsigned*)(orow1 + col) = hpair(__float2half_rn(oacc[j*4 + 0] * linv1),
                                          __float2half_rn(oacc[j*4 + 1] * linv1));
        *(unsigned*)(orow2 + col) = hpair(__float2half_rn(oacc[j*4 + 2] * linv2),
                                          __float2half_rn(oacc[j*4 + 3] * linv2));
    }
}

// ============================================================
// K4: combine the H rounds.  Warp = 1 token, lane = half2 dim pair.
// ============================================================
__global__ __launch_bounds__(256) void combine_kernel(float* __restrict__ out)
{
    int bt = blockIdx.x * 8 + (threadIdx.x >> 5);
    int b = bt >> 13, t = bt & (S - 1);
    int d2 = threadIdx.x & 31;

    float lg[H];
    float mx = -INFINITY;
    size_t lbase = ((size_t)b * H) * S + t;
#pragma unroll
    for (int h = 0; h < H; h++) {
        lg[h] = g_logits[lbase + (size_t)h * S];
        mx = fmaxf(mx, lg[h]);
    }
    float sum = 0.f;
#pragma unroll
    for (int h = 0; h < H; h++) { lg[h] = __expf(lg[h] - mx); sum += lg[h]; }

    float a0 = 0.f, a1 = 0.f;
#pragma unroll
    for (int h = 0; h < H; h++) {
        __half2 v = *(const __half2*)(g_o + ((lbase + (size_t)h * S) * D) + 2 * d2);
        float2 vf = __half22float2(v);
        a0 += lg[h] * vf.x;
        a1 += lg[h] * vf.y;
    }

    float inv = 1.f / sum;
    *(float2*)(out + ((size_t)b * S + t) * D + 2 * d2) = make_float2(a0 * inv, a1 * inv);
}

// ============================================================
extern "C" void kernel_launch(void* const* d_in, const int* in_sizes, int n_in,
                              void* d_out, int out_size)
{
    const float* qk  = (const float*)d_in[0];
    const float* v   = (const float*)d_in[1];
    const float* rot = (const float*)d_in[2];
    float* out = (float*)d_out;

    cudaFuncSetAttribute(attn_kernel, cudaFuncAttributeMaxDynamicSharedMemorySize, ATTN_SMEM_B);
    cudaFuncSetAttribute(hash_kernel, cudaFuncAttributeMaxDynamicSharedMemorySize, HASH_SMEM_B);

    prep_kernel<<<B * S * 16 / 256, 256>>>(qk, v);
    hash_kernel<<<dim3(S / 128, H, B), 128, HASH_SMEM_B>>>(qk, rot);
    sort_kernel<<<B * H, 256>>>();
    attn_kernel<<<dim3(CHUNKS, B), 128, ATTN_SMEM_B>>>();
    combine_kernel<<<B * S / 8, 256>>>(out);
}